// round 12
// baseline (speedup 1.0000x reference)
#include <cuda_runtime.h>
#include <cuda.h>
#include <cuda_bf16.h>
#include <cstdint>

// ---------------------------------------------------------------------------
// Problem constants
// ---------------------------------------------------------------------------
#define TOKENS 8192
#define IN_F   4096
#define OUT_F  16384

#define TILE_MP 256                  // M per cluster pair (128 per CTA)
#define TILE_NP 512                  // N per cluster pair (2 x N=256 MMAs)
#define GTHREADS 128
#define CLUSTER 2

// SW64 atoms: 32 bf16 per stage-row (64B rows)
#define KC     32
#define NKI    (IN_F / KC)           // 128 K-iterations
#define NSTAGE 8                     // power of two: stage = ks&7, phase = (ks>>3)&1
#define RLAG   3                     // refill lag: gate on DONE of stage used 3 iters ago

// Per-CTA shared memory stage: A 128x64B (8KB) + B 2x128x64B (16KB) = 24KB
#define SM_TMEMPTR 0
#define SM_FULL(s)  (64  + (s) * 8)   // local TMA completion (expect_tx)
#define SM_DONE(s)  (192 + (s) * 8)   // leader's cg2 multicast commit
#define SM_PRDY(s)  (320 + (s) * 8)   // leader-only: peer stage-ready arrives
#define SM_FINAL    448
#define SM_TILES    1024
#define A_BYTES     (128 * KC * 2)            // 8192
#define B_CHUNK     (128 * KC * 2)            // 8192
#define STAGE_BYTES (A_BYTES + 2 * B_CHUNK)   // 24576
#define SM_A(s) (SM_TILES + (s) * STAGE_BYTES)
#define SM_B(s) (SM_A(s) + A_BYTES)
#define SMEM_TOTAL (SM_TILES + NSTAGE * STAGE_BYTES)  // 197632

// Arch-specific feature gate: tcgen05 legal only on sm_100a / sm_103a targets.
#if defined(__CUDA_ARCH_FEAT_SM103_ALL) || defined(__CUDA_ARCH_FEAT_SM100_ALL)
#define HAS_TCGEN05 1
#else
#define HAS_TCGEN05 0
#endif

// idesc, kind::f16 cg2: dtype=F32, a=BF16, b=BF16, N=256 -> (N/8)<<17,
// M_TOTAL=256 -> (256/16)<<24.  (Validated R11: passed, rel_err 5.7e-8.)
static constexpr uint32_t MMA_IDESC_CG2 =
    (1u << 4) | (1u << 7) | (1u << 10) | ((256u / 8u) << 17) | ((256u / 16u) << 24);

// Scratch (device-global scratch is the sanctioned no-alloc path).
__device__ __nv_bfloat16 g_xb[(size_t)TOKENS * IN_F];   // 64 MB
__device__ __nv_bfloat16 g_wb[(size_t)OUT_F * IN_F];    // 128 MB

// ---------------------------------------------------------------------------
// Common PTX helpers
// ---------------------------------------------------------------------------
__device__ __forceinline__ uint32_t elect_one_pred() {
    uint32_t pred;
    asm volatile(
        "{\n\t.reg .pred p;\n\telect.sync _|p, 0xFFFFFFFF;\n\t"
        "selp.b32 %0, 1, 0, p;\n\t}" : "=r"(pred));
    return pred;
}

__device__ __forceinline__ uint32_t smem_u32(const void* p) {
    uint32_t a;
    asm("{ .reg .u64 t; cvta.to.shared.u64 t, %1; cvt.u32.u64 %0, t; }"
        : "=r"(a) : "l"(p));
    return a;
}

#define MBARRIER_INIT(addr, cnt) \
    asm volatile("mbarrier.init.shared.b64 [%0], %1;" :: "r"((uint32_t)(addr)), "r"((uint32_t)(cnt)) : "memory")

#define MBARRIER_EXPECT_TX(addr, tx) \
    asm volatile("mbarrier.arrive.expect_tx.shared.b64 _, [%0], %1;" :: "r"((uint32_t)(addr)), "r"((uint32_t)(tx)) : "memory")

// Arrive on the mbarrier at the same SMEM offset in cluster CTA `rank`.
#define MBARRIER_ARRIVE_CLUSTER(local_mbar_addr, target_rank) \
    asm volatile( \
        "{\n\t.reg .b32 remAddr32;\n\t" \
        "mapa.shared::cluster.u32 remAddr32, %0, %1;\n\t" \
        "mbarrier.arrive.shared::cluster.b64 _, [remAddr32];\n\t}" \
        :: "r"((uint32_t)(local_mbar_addr)), "r"((uint32_t)(target_rank)) : "memory")

#define MBARRIER_WAIT_PARITY(mbar_smem_addr, phase_parity) do { \
    uint32_t _mbar = (uint32_t)(mbar_smem_addr); \
    uint32_t _parity = (uint32_t)(phase_parity); \
    uint32_t _done_; \
    asm volatile( \
        "{\n\t.reg .pred p;\n\t" \
        "mbarrier.try_wait.parity.acquire.cta.shared::cta.b64 p, [%1], %2;\n\t" \
        "selp.b32 %0, 1, 0, p;\n\t}" \
        : "=r"(_done_) : "r"(_mbar), "r"(_parity) : "memory"); \
    if (!_done_) { \
        asm volatile( \
            "{\n\t.reg .pred P1;\n\t" \
            "WAIT_LOOP_%=:\n\t" \
            "mbarrier.try_wait.parity.acquire.cta.shared::cta.b64 P1, [%0], %1, 0x989680;\n\t" \
            "@P1 bra.uni WAIT_DONE_%=;\n\t" \
            "bra.uni WAIT_LOOP_%=;\n\t" \
            "WAIT_DONE_%=:\n\t}" \
            :: "r"(_mbar), "r"(_parity) : "memory"); \
    } \
} while (0)

#define CLUSTER_SYNC() do { \
    asm volatile("barrier.cluster.arrive.aligned;" ::: "memory"); \
    asm volatile("barrier.cluster.wait.aligned;"   ::: "memory"); \
} while (0)

// ---------------------------------------------------------------------------
// tcgen05 cg2 macros (only EXPANDED inside HAS_TCGEN05 regions)
// ---------------------------------------------------------------------------
#define TCGEN05_ALLOC_CG2(smem_result_addr, nCols) \
    asm volatile("tcgen05.alloc.cta_group::2.sync.aligned.shared::cta.b32 [%0], %1;" \
        :: "r"((uint32_t)(smem_result_addr)), "r"((uint32_t)(nCols)) : "memory")

#define TCGEN05_DEALLOC_CG2(tmem_addr, nCols) \
    asm volatile("tcgen05.dealloc.cta_group::2.sync.aligned.b32 %0, %1;" \
        :: "r"(tmem_addr), "r"((uint32_t)(nCols)))

#define TCGEN05_RELINQUISH_CG2() \
    asm volatile("tcgen05.relinquish_alloc_permit.cta_group::2.sync.aligned;")

#define TCGEN05_COMMIT_MC_CG2(mbar_smem_addr, mask) \
    asm volatile("tcgen05.commit.cta_group::2.mbarrier::arrive::one.shared::cluster.multicast::cluster.b64 [%0], %1;" \
        :: "r"((uint32_t)(mbar_smem_addr)), "h"((uint16_t)(mask)) : "memory")

#define TCGEN05_WAIT_LD() \
    asm volatile("tcgen05.wait::ld.sync.aligned;" ::: "memory")

#define TCGEN05_FENCE_BEFORE() \
    asm volatile("tcgen05.fence::before_thread_sync;" ::: "memory")

#define TCGEN05_FENCE_AFTER() \
    asm volatile("tcgen05.fence::after_thread_sync;" ::: "memory")

#define TCGEN05_LD_32X32B_X32(r, tmem_addr) \
    asm volatile( \
        "tcgen05.ld.sync.aligned.32x32b.x32.b32 " \
        "{%0, %1, %2, %3, %4, %5, %6, %7, " \
        " %8, %9, %10, %11, %12, %13, %14, %15, " \
        " %16, %17, %18, %19, %20, %21, %22, %23, " \
        " %24, %25, %26, %27, %28, %29, %30, %31}, [%32];" \
        : "=r"((r)[0]),  "=r"((r)[1]),  "=r"((r)[2]),  "=r"((r)[3]), \
          "=r"((r)[4]),  "=r"((r)[5]),  "=r"((r)[6]),  "=r"((r)[7]), \
          "=r"((r)[8]),  "=r"((r)[9]),  "=r"((r)[10]), "=r"((r)[11]), \
          "=r"((r)[12]), "=r"((r)[13]), "=r"((r)[14]), "=r"((r)[15]), \
          "=r"((r)[16]), "=r"((r)[17]), "=r"((r)[18]), "=r"((r)[19]), \
          "=r"((r)[20]), "=r"((r)[21]), "=r"((r)[22]), "=r"((r)[23]), \
          "=r"((r)[24]), "=r"((r)[25]), "=r"((r)[26]), "=r"((r)[27]), \
          "=r"((r)[28]), "=r"((r)[29]), "=r"((r)[30]), "=r"((r)[31]) \
        : "r"(tmem_addr))

// SW64 K-major descriptor: layout=4, version=1, SBO=32 (512B atom), LBO=1.
static constexpr unsigned long long SMEM_DESC_BASE_SW64 =
    (4ull << 61) | (1ull << 46) | (32ull << 32) | (1ull << 16);

__device__ __forceinline__ uint64_t make_desc64(uint32_t smem_addr) {
    return SMEM_DESC_BASE_SW64 | ((uint64_t)(smem_addr >> 4) & 0x3FFFull);
}

#if HAS_TCGEN05
// cg2 bf16 SS MMA (8 zero regs for disable-output-lane, per the cg2 example).
__device__ __forceinline__ void mma_bf16_ss_cg2(uint32_t d_tmem, uint64_t a_desc,
                                                uint64_t b_desc, uint32_t idesc,
                                                uint32_t enable_d) {
    asm volatile(
        "{\n\t.reg .pred p;\n\t"
        "setp.ne.u32 p, %5, 0;\n\t"
        "tcgen05.mma.cta_group::2.kind::f16 [%0], %1, %2, %3, "
        "{%4, %4, %4, %4, %4, %4, %4, %4}, p;\n\t}"
        :: "r"(d_tmem), "l"(a_desc), "l"(b_desc), "r"(idesc), "r"(0u), "r"(enable_d)
        : "memory");
}

__device__ __forceinline__ void tma_ld2(uint32_t smem_addr, const CUtensorMap* tmap,
                                        int cx, int cy, uint32_t mbar) {
    asm volatile(
        "cp.async.bulk.tensor.2d.shared::cta.global.tile.mbarrier::complete_tx::bytes "
        "[%0], [%1, {%2, %3}], [%4];"
        :: "r"(smem_addr), "l"(tmap), "r"(cx), "r"(cy), "r"(mbar) : "memory");
}
#endif

// ---------------------------------------------------------------------------
// Fallback helpers: ldmatrix + int8 mma.sync (family-portable)
// ---------------------------------------------------------------------------
__device__ __forceinline__ void ldsm_x4(uint32_t& r0, uint32_t& r1,
                                        uint32_t& r2, uint32_t& r3, uint32_t addr) {
    asm volatile("ldmatrix.sync.aligned.m8n8.x4.shared.b16 {%0,%1,%2,%3}, [%4];"
                 : "=r"(r0), "=r"(r1), "=r"(r2), "=r"(r3) : "r"(addr));
}

__device__ __forceinline__ void imma16832(int* c, const uint32_t* a, const uint32_t* b) {
    asm volatile(
        "mma.sync.aligned.m16n8k32.row.col.s32.s8.s8.s32 "
        "{%0,%1,%2,%3}, {%4,%5,%6,%7}, {%8,%9}, {%0,%1,%2,%3};"
        : "+r"(c[0]), "+r"(c[1]), "+r"(c[2]), "+r"(c[3])
        : "r"(a[0]), "r"(a[1]), "r"(a[2]), "r"(a[3]), "r"(b[0]), "r"(b[1]));
}

// ---------------------------------------------------------------------------
// Pre-pass: int32 -> bf16 (tcgen05 path) or int8 (fallback path)
// ---------------------------------------------------------------------------
__global__ void cvt_kernel(const int4* __restrict__ in, void* __restrict__ out, int n4) {
    int i = blockIdx.x * blockDim.x + threadIdx.x;
    if (i >= n4) return;
    int4 v = in[i];
#if HAS_TCGEN05
    __nv_bfloat162 p0, p1;
    p0.x = __int2bfloat16_rn(v.x); p0.y = __int2bfloat16_rn(v.y);
    p1.x = __int2bfloat16_rn(v.z); p1.y = __int2bfloat16_rn(v.w);
    uint2 o;
    o.x = *reinterpret_cast<unsigned*>(&p0);
    o.y = *reinterpret_cast<unsigned*>(&p1);
    reinterpret_cast<uint2*>(out)[i] = o;
#else
    char4 o;
    o.x = (char)v.x; o.y = (char)v.y; o.z = (char)v.z; o.w = (char)v.w;
    reinterpret_cast<char4*>(out)[i] = o;
#endif
}

// ---------------------------------------------------------------------------
// GEMM: cg2 pair computes 256x512 (48B L2 traffic per output).
// Refill gate lagged RLAG=3 iterations: DONE waits hit the try_wait fast path
// instead of blocking on MMA drain + cluster-hop (R11 lesson).
// ---------------------------------------------------------------------------
__global__ void __launch_bounds__(GTHREADS) __cluster_dims__(CLUSTER, 1, 1)
q8gemm_kernel(
    const __grid_constant__ CUtensorMap tmA,
    const __grid_constant__ CUtensorMap tmB,
    const float* __restrict__ bias,
    const float* __restrict__ xsc,
    const float* __restrict__ wsc,
    float* __restrict__ out)
{
    extern __shared__ __align__(1024) char smem[];
    const int tid = threadIdx.x;
    const int wid = tid >> 5;
    const int lid = tid & 31;

    // Pair rasterization: 32 m-pairs x 32 n-tiles; 8-n-tile bands keep a 32MB
    // B band L2-resident.
    const int rank = blockIdx.x & 1;             // == cluster rank (dim x = 2)
    const int pair = blockIdx.x >> 1;            // 0..1023
    const int band = pair / (8 * 32);
    const int r    = pair % (8 * 32);
    const int mtp  = r / 8;
    const int nt   = band * 8 + (r % 8);
    const int m0c  = mtp * TILE_MP + rank * 128; // this CTA's 128 rows
    const int n0   = nt * TILE_NP;               // 512-wide N tile

#if HAS_TCGEN05
    // ======================= tcgen05 cg2 bf16 path =======================
    const uint32_t sb = smem_u32(smem);

    if (wid == 0) TCGEN05_ALLOC_CG2(sb + SM_TMEMPTR, 512);
    if (tid == 0) {
        #pragma unroll
        for (int s = 0; s < NSTAGE; s++) {
            MBARRIER_INIT(sb + SM_FULL(s), 1);   // local expect_tx arrive
            MBARRIER_INIT(sb + SM_DONE(s), 1);   // leader's multicast commit
            MBARRIER_INIT(sb + SM_PRDY(s), 1);   // peer stage-ready (leader-side)
        }
        MBARRIER_INIT(sb + SM_FINAL, 1);
    }
    __syncthreads();
    CLUSTER_SYNC();   // peer barriers live before any cross-CTA arrive/commit

    uint32_t tbase;
    asm volatile("ld.shared.b32 %0, [%1];" : "=r"(tbase) : "r"(sb + SM_TMEMPTR));

    if (wid == 0) {
        // Prologue: each CTA fills all its stages (A half + two B chunks).
        if (elect_one_pred()) {
            #pragma unroll
            for (int s = 0; s < NSTAGE; s++) {
                MBARRIER_EXPECT_TX(sb + SM_FULL(s), STAGE_BYTES);
                tma_ld2(sb + SM_A(s),           &tmA, s * KC, m0c,                   sb + SM_FULL(s));
                tma_ld2(sb + SM_B(s),           &tmB, s * KC, n0 + rank * 128,       sb + SM_FULL(s));
                tma_ld2(sb + SM_B(s) + B_CHUNK, &tmB, s * KC, n0 + 256 + rank * 128, sb + SM_FULL(s));
            }
        }
        if (rank == 0) {
            // ---- leader: MMA driver ----
            for (int ks = 0; ks < NKI; ks++) {
                const int st = ks & (NSTAGE - 1);
                const int ph = (ks >> 3) & 1;
                MBARRIER_WAIT_PARITY(sb + SM_FULL(st), ph);   // my slices ready
                MBARRIER_WAIT_PARITY(sb + SM_PRDY(st), ph);   // peer ready (fast-path: arrived >=5 iters ago)
                if (elect_one_pred()) {
                    uint64_t ad = make_desc64(sb + SM_A(st));
                    uint64_t b0 = make_desc64(sb + SM_B(st));
                    uint64_t b1 = make_desc64(sb + SM_B(st) + B_CHUNK);
                    #pragma unroll
                    for (int j = 0; j < 2; j++) {             // 2 x K16 = K32
                        uint32_t e = (uint32_t)((ks | j) != 0);
                        mma_bf16_ss_cg2(tbase,       ad + j * 2, b0 + j * 2, MMA_IDESC_CG2, e);
                        mma_bf16_ss_cg2(tbase + 256, ad + j * 2, b1 + j * 2, MMA_IDESC_CG2, e);
                    }
                    TCGEN05_COMMIT_MC_CG2(sb + SM_DONE(st), 0x3);
                }
                // Lagged refill: stage consumed at rs = ks-RLAG; its DONE flipped
                // ~2 iterations ago, so this wait is a fast-path probe, not a
                // blocking MMA-drain + cluster-hop (R11's critical-path bug).
                const int rs = ks - RLAG;
                if (rs >= 0 && rs + NSTAGE < NKI) {
                    const int rst = rs & (NSTAGE - 1);
                    const int rph = (rs >> 3) & 1;
                    MBARRIER_WAIT_PARITY(sb + SM_DONE(rst), rph);
                    if (elect_one_pred()) {
                        MBARRIER_EXPECT_TX(sb + SM_FULL(rst), STAGE_BYTES);
                        const int kk = rs + NSTAGE;
                        tma_ld2(sb + SM_A(rst),           &tmA, kk * KC, m0c,                   sb + SM_FULL(rst));
                        tma_ld2(sb + SM_B(rst),           &tmB, kk * KC, n0 + rank * 128,       sb + SM_FULL(rst));
                        tma_ld2(sb + SM_B(rst) + B_CHUNK, &tmB, kk * KC, n0 + 256 + rank * 128, sb + SM_FULL(rst));
                    }
                }
            }
            if (elect_one_pred()) TCGEN05_COMMIT_MC_CG2(sb + SM_FINAL, 0x3);
        } else {
            // ---- peer: readiness forwarder + refiller (no MMA waits) ----
            for (int ks = 0; ks < NKI; ks++) {
                const int st = ks & (NSTAGE - 1);
                const int ph = (ks >> 3) & 1;
                MBARRIER_WAIT_PARITY(sb + SM_FULL(st), ph);   // my TMAs landed
                if (elect_one_pred()) MBARRIER_ARRIVE_CLUSTER(sb + SM_PRDY(st), 0);
                const int rs = ks - RLAG;
                if (rs >= 0 && rs + NSTAGE < NKI) {
                    const int rst = rs & (NSTAGE - 1);
                    const int rph = (rs >> 3) & 1;
                    MBARRIER_WAIT_PARITY(sb + SM_DONE(rst), rph);  // fast-path probe
                    if (elect_one_pred()) {
                        MBARRIER_EXPECT_TX(sb + SM_FULL(rst), STAGE_BYTES);
                        const int kk = rs + NSTAGE;
                        tma_ld2(sb + SM_A(rst),           &tmA, kk * KC, m0c,                   sb + SM_FULL(rst));
                        tma_ld2(sb + SM_B(rst),           &tmB, kk * KC, n0 + rank * 128,       sb + SM_FULL(rst));
                        tma_ld2(sb + SM_B(rst) + B_CHUNK, &tmB, kk * KC, n0 + 256 + rank * 128, sb + SM_FULL(rst));
                    }
                }
            }
        }
    }

    // Epilogue: each CTA reads its own 128 rows x 512 cols from TMEM.
    MBARRIER_WAIT_PARITY(sb + SM_FINAL, 0);
    TCGEN05_FENCE_AFTER();

    float* s_ws = reinterpret_cast<float*>(smem + SM_TILES);   // stage area is dead
    float* s_bi = s_ws + TILE_NP;
    for (int i = tid; i < TILE_NP; i += GTHREADS) {
        s_ws[i] = wsc[n0 + i];
        s_bi[i] = bias[n0 + i];
    }
    __syncthreads();

    const int row = m0c + wid * 32 + lid;
    const float xsv = xsc[row];
    float* orow = out + (size_t)row * OUT_F + n0;

    #pragma unroll 1
    for (int cb = 0; cb < TILE_NP / 32; cb++) {    // 16 column blocks
        uint32_t rg[32];
        TCGEN05_LD_32X32B_X32(rg, tbase + cb * 32);
        TCGEN05_WAIT_LD();
        #pragma unroll
        for (int q = 0; q < 8; q++) {
            const int c = cb * 32 + q * 4;
            float4 v;
            v.x = fmaf(__uint_as_float(rg[q * 4 + 0]), xsv * s_ws[c + 0], s_bi[c + 0]);
            v.y = fmaf(__uint_as_float(rg[q * 4 + 1]), xsv * s_ws[c + 1], s_bi[c + 1]);
            v.z = fmaf(__uint_as_float(rg[q * 4 + 2]), xsv * s_ws[c + 2], s_bi[c + 2]);
            v.w = fmaf(__uint_as_float(rg[q * 4 + 3]), xsv * s_ws[c + 3], s_bi[c + 3]);
            *reinterpret_cast<float4*>(orow + c) = v;
        }
    }
    TCGEN05_FENCE_BEFORE();
    __syncthreads();
    if (wid == 0) {
        TCGEN05_RELINQUISH_CG2();
        TCGEN05_DEALLOC_CG2(tbase, 512);
    }
    CLUSTER_SYNC();   // no CTA exits while peer traffic may be in flight

#else
    // =================== portable int8 mma.sync fallback ===================
    // Each CTA computes its 128 rows x 512 cols independently.
    const int8_t* x8 = reinterpret_cast<const int8_t*>(g_xb);
    const int8_t* w8 = reinterpret_cast<const int8_t*>(g_wb);

    const int AST = 80, BST = 80;
    char* sA = smem;
    char* sB = smem + 128 * AST;
    const uint32_t sAu = smem_u32(sA);
    const uint32_t sBu = smem_u32(sB);
    const int warp_row = wid * 32;

    for (int nc = 0; nc < 8; nc++) {               // 8 x 64-col chunks of 512
        const int nb = n0 + nc * 64;
        int acc[2][8][4];
        #pragma unroll
        for (int a = 0; a < 2; a++)
            #pragma unroll
            for (int b = 0; b < 8; b++)
                #pragma unroll
                for (int c = 0; c < 4; c++) acc[a][b][c] = 0;

        for (int kt = 0; kt < 64; kt++) {
            const int k0 = kt * 64;
            __syncthreads();
            {
                const uint4* src = reinterpret_cast<const uint4*>(
                    x8 + (size_t)(m0c + tid) * IN_F + k0);
                uint4* dst = reinterpret_cast<uint4*>(sA + tid * AST);
                #pragma unroll
                for (int j = 0; j < 4; j++) dst[j] = src[j];
            }
            {
                const int br = tid >> 1, hh = tid & 1;
                const uint4* src = reinterpret_cast<const uint4*>(
                    w8 + (size_t)(nb + br) * IN_F + k0 + hh * 32);
                uint4* dst = reinterpret_cast<uint4*>(sB + br * BST + hh * 32);
                dst[0] = src[0]; dst[1] = src[1];
            }
            __syncthreads();

            #pragma unroll
            for (int s = 0; s < 2; s++) {
                uint32_t afr[2][4];
                #pragma unroll
                for (int mt2 = 0; mt2 < 2; mt2++) {
                    uint32_t addr = sAu +
                        (uint32_t)(warp_row + mt2 * 16 + (lid & 15)) * AST +
                        s * 32 + ((lid >= 16) ? 16 : 0);
                    ldsm_x4(afr[mt2][0], afr[mt2][1], afr[mt2][2], afr[mt2][3], addr);
                }
                uint32_t bfr[4][4];
                #pragma unroll
                for (int p = 0; p < 4; p++) {
                    uint32_t addr = sBu +
                        (uint32_t)(p * 16 + (lid & 7) + ((lid >= 16) ? 8 : 0)) * BST +
                        s * 32 + ((lid & 8) ? 16 : 0);
                    ldsm_x4(bfr[p][0], bfr[p][1], bfr[p][2], bfr[p][3], addr);
                }
                #pragma unroll
                for (int mt2 = 0; mt2 < 2; mt2++)
                    #pragma unroll
                    for (int nt2 = 0; nt2 < 8; nt2++) {
                        uint32_t bb[2];
                        bb[0] = bfr[nt2 >> 1][(nt2 & 1) ? 2 : 0];
                        bb[1] = bfr[nt2 >> 1][(nt2 & 1) ? 3 : 1];
                        imma16832(acc[mt2][nt2], afr[mt2], bb);
                    }
            }
        }
        #pragma unroll
        for (int mt2 = 0; mt2 < 2; mt2++) {
            const int r0_ = m0c + warp_row + mt2 * 16 + (lid >> 2);
            const float xs0 = xsc[r0_], xs1 = xsc[r0_ + 8];
            #pragma unroll
            for (int nt2 = 0; nt2 < 8; nt2++) {
                const int c0 = nb + nt2 * 8 + (lid & 3) * 2;
                const float w0 = wsc[c0], w1 = wsc[c0 + 1];
                const float b0 = bias[c0], b1 = bias[c0 + 1];
                float* o0 = out + (size_t)r0_ * OUT_F + c0;
                float* o1 = out + (size_t)(r0_ + 8) * OUT_F + c0;
                o0[0] = fmaf((float)acc[mt2][nt2][0], xs0 * w0, b0);
                o0[1] = fmaf((float)acc[mt2][nt2][1], xs0 * w1, b1);
                o1[0] = fmaf((float)acc[mt2][nt2][2], xs1 * w0, b0);
                o1[1] = fmaf((float)acc[mt2][nt2][3], xs1 * w1, b1);
            }
        }
    }
#endif
}

// ---------------------------------------------------------------------------
// Host launcher
// ---------------------------------------------------------------------------
typedef CUresult (*tmencode_fn_t)(
    CUtensorMap*, CUtensorMapDataType, cuuint32_t, void*,
    const cuuint64_t*, const cuuint64_t*, const cuuint32_t*, const cuuint32_t*,
    CUtensorMapInterleave, CUtensorMapSwizzle, CUtensorMapL2promotion,
    CUtensorMapFloatOOBfill);

extern "C" void kernel_launch(void* const* d_in, const int* in_sizes, int n_in,
                              void* d_out, int out_size) {
    const int*   x    = (const int*)d_in[0];
    const int*   w    = (const int*)d_in[1];
    const float* bias = (const float*)d_in[2];
    const float* xsc  = (const float*)d_in[3];
    const float* wsc  = (const float*)d_in[4];
    float* out = (float*)d_out;

    void* xb_ptr = nullptr;
    void* wb_ptr = nullptr;
    cudaGetSymbolAddress(&xb_ptr, g_xb);
    cudaGetSymbolAddress(&wb_ptr, g_wb);

    // Pre-pass: int32 -> (bf16 | int8), matching whichever GEMM variant loads.
    {
        int n4x = TOKENS * IN_F / 4;
        int n4w = OUT_F * IN_F / 4;
        cvt_kernel<<<(n4x + 255) / 256, 256>>>((const int4*)x, xb_ptr, n4x);
        cvt_kernel<<<(n4w + 255) / 256, 256>>>((const int4*)w, wb_ptr, n4w);
    }

    // TMA descriptors: SW64, 64B inner rows, 128-row boxes (A half / B chunk).
    tmencode_fn_t enc = nullptr;
    {
        void* fn = nullptr;
        cudaDriverEntryPointQueryResult qres;
#if CUDART_VERSION >= 12050
        cudaGetDriverEntryPointByVersion("cuTensorMapEncodeTiled", &fn, 12000,
                                         cudaEnableDefault, &qres);
#else
        cudaGetDriverEntryPoint("cuTensorMapEncodeTiled", &fn,
                                cudaEnableDefault, &qres);
#endif
        enc = (tmencode_fn_t)fn;
    }

    alignas(64) CUtensorMap tmA, tmB;
    if (enc) {
        {
            cuuint64_t dims[2] = {IN_F, TOKENS};
            cuuint64_t strd[1] = {IN_F * 2ull};
            cuuint32_t box[2]  = {KC, 128};
            cuuint32_t es[2]   = {1, 1};
            enc(&tmA, CU_TENSOR_MAP_DATA_TYPE_BFLOAT16, 2, xb_ptr, dims, strd, box, es,
                CU_TENSOR_MAP_INTERLEAVE_NONE, CU_TENSOR_MAP_SWIZZLE_64B,
                CU_TENSOR_MAP_L2_PROMOTION_L2_128B, CU_TENSOR_MAP_FLOAT_OOB_FILL_NONE);
        }
        {
            cuuint64_t dims[2] = {IN_F, OUT_F};
            cuuint64_t strd[1] = {IN_F * 2ull};
            cuuint32_t box[2]  = {KC, 128};
            cuuint32_t es[2]   = {1, 1};
            enc(&tmB, CU_TENSOR_MAP_DATA_TYPE_BFLOAT16, 2, wb_ptr, dims, strd, box, es,
                CU_TENSOR_MAP_INTERLEAVE_NONE, CU_TENSOR_MAP_SWIZZLE_64B,
                CU_TENSOR_MAP_L2_PROMOTION_L2_128B, CU_TENSOR_MAP_FLOAT_OOB_FILL_NONE);
        }
    }

    cudaFuncSetAttribute(q8gemm_kernel,
                         cudaFuncAttributeMaxDynamicSharedMemorySize, SMEM_TOTAL);

    const int grid = (TOKENS / TILE_MP) * (OUT_F / TILE_NP) * CLUSTER;  // 2048
    q8gemm_kernel<<<grid, GTHREADS, SMEM_TOTAL>>>(tmA, tmB, bias, xsc, wsc, out);
}

// round 13
// speedup vs baseline: 1.0079x; 1.0079x over previous
#include <cuda_runtime.h>
#include <cuda.h>
#include <cuda_bf16.h>
#include <cstdint>

// ---------------------------------------------------------------------------
// Problem constants
// ---------------------------------------------------------------------------
#define TOKENS 8192
#define IN_F   4096
#define OUT_F  16384

#define TILE_MP 256                  // M per cluster pair (128 per CTA)
#define TILE_NP 512                  // N per cluster pair (2 x N=256 MMAs)
#define GTHREADS 128
#define CLUSTER 2

// SW128 atoms: 64 bf16 per stage-row (128B rows) — validated R5/R9/R10
#define KC     64
#define NKI    (IN_F / KC)           // 64 K-iterations
#define NSTAGE 4                     // stage = ks&3, phase = (ks>>2)&1

// Per-CTA stage: A 128x128B (16KB) + B 2x128x128B (32KB) = 48KB
#define SM_TMEMPTR 0
#define SM_FULL(s)  (64  + (s) * 8)   // local TMA completion (expect_tx)
#define SM_DONE(s)  (192 + (s) * 8)   // leader's cg2 multicast commit
#define SM_PRDY(s)  (320 + (s) * 8)   // leader-only: peer stage-ready arrives
#define SM_FINAL    448
#define SM_TILES    1024
#define A_BYTES     (128 * KC * 2)            // 16384
#define B_CHUNK     (128 * KC * 2)            // 16384
#define STAGE_BYTES (A_BYTES + 2 * B_CHUNK)   // 49152
#define SM_A(s) (SM_TILES + (s) * STAGE_BYTES)
#define SM_B(s) (SM_A(s) + A_BYTES)
#define SMEM_TOTAL (SM_TILES + NSTAGE * STAGE_BYTES)  // 197632

// Arch-specific feature gate: tcgen05 legal only on sm_100a / sm_103a targets.
#if defined(__CUDA_ARCH_FEAT_SM103_ALL) || defined(__CUDA_ARCH_FEAT_SM100_ALL)
#define HAS_TCGEN05 1
#else
#define HAS_TCGEN05 0
#endif

// idesc, kind::f16 cg2: dtype=F32, a=BF16, b=BF16, N=256, M_TOTAL=256.
// (Validated R11/R12: passed, rel_err 5.7e-8.)
static constexpr uint32_t MMA_IDESC_CG2 =
    (1u << 4) | (1u << 7) | (1u << 10) | ((256u / 8u) << 17) | ((256u / 16u) << 24);

// Scratch (device-global scratch is the sanctioned no-alloc path).
__device__ __nv_bfloat16 g_xb[(size_t)TOKENS * IN_F];   // 64 MB
__device__ __nv_bfloat16 g_wb[(size_t)OUT_F * IN_F];    // 128 MB

// ---------------------------------------------------------------------------
// Common PTX helpers
// ---------------------------------------------------------------------------
__device__ __forceinline__ uint32_t elect_one_pred() {
    uint32_t pred;
    asm volatile(
        "{\n\t.reg .pred p;\n\telect.sync _|p, 0xFFFFFFFF;\n\t"
        "selp.b32 %0, 1, 0, p;\n\t}" : "=r"(pred));
    return pred;
}

__device__ __forceinline__ uint32_t smem_u32(const void* p) {
    uint32_t a;
    asm("{ .reg .u64 t; cvta.to.shared.u64 t, %1; cvt.u32.u64 %0, t; }"
        : "=r"(a) : "l"(p));
    return a;
}

#define MBARRIER_INIT(addr, cnt) \
    asm volatile("mbarrier.init.shared.b64 [%0], %1;" :: "r"((uint32_t)(addr)), "r"((uint32_t)(cnt)) : "memory")

#define MBARRIER_EXPECT_TX(addr, tx) \
    asm volatile("mbarrier.arrive.expect_tx.shared.b64 _, [%0], %1;" :: "r"((uint32_t)(addr)), "r"((uint32_t)(tx)) : "memory")

// Arrive on the mbarrier at the same SMEM offset in cluster CTA `rank`.
#define MBARRIER_ARRIVE_CLUSTER(local_mbar_addr, target_rank) \
    asm volatile( \
        "{\n\t.reg .b32 remAddr32;\n\t" \
        "mapa.shared::cluster.u32 remAddr32, %0, %1;\n\t" \
        "mbarrier.arrive.shared::cluster.b64 _, [remAddr32];\n\t}" \
        :: "r"((uint32_t)(local_mbar_addr)), "r"((uint32_t)(target_rank)) : "memory")

#define MBARRIER_WAIT_PARITY(mbar_smem_addr, phase_parity) do { \
    uint32_t _mbar = (uint32_t)(mbar_smem_addr); \
    uint32_t _parity = (uint32_t)(phase_parity); \
    uint32_t _done_; \
    asm volatile( \
        "{\n\t.reg .pred p;\n\t" \
        "mbarrier.try_wait.parity.acquire.cta.shared::cta.b64 p, [%1], %2;\n\t" \
        "selp.b32 %0, 1, 0, p;\n\t}" \
        : "=r"(_done_) : "r"(_mbar), "r"(_parity) : "memory"); \
    if (!_done_) { \
        asm volatile( \
            "{\n\t.reg .pred P1;\n\t" \
            "WAIT_LOOP_%=:\n\t" \
            "mbarrier.try_wait.parity.acquire.cta.shared::cta.b64 P1, [%0], %1, 0x989680;\n\t" \
            "@P1 bra.uni WAIT_DONE_%=;\n\t" \
            "bra.uni WAIT_LOOP_%=;\n\t" \
            "WAIT_DONE_%=:\n\t}" \
            :: "r"(_mbar), "r"(_parity) : "memory"); \
    } \
} while (0)

#define CLUSTER_SYNC() do { \
    asm volatile("barrier.cluster.arrive.aligned;" ::: "memory"); \
    asm volatile("barrier.cluster.wait.aligned;"   ::: "memory"); \
} while (0)

// ---------------------------------------------------------------------------
// tcgen05 cg2 macros (only EXPANDED inside HAS_TCGEN05 regions)
// ---------------------------------------------------------------------------
#define TCGEN05_ALLOC_CG2(smem_result_addr, nCols) \
    asm volatile("tcgen05.alloc.cta_group::2.sync.aligned.shared::cta.b32 [%0], %1;" \
        :: "r"((uint32_t)(smem_result_addr)), "r"((uint32_t)(nCols)) : "memory")

#define TCGEN05_DEALLOC_CG2(tmem_addr, nCols) \
    asm volatile("tcgen05.dealloc.cta_group::2.sync.aligned.b32 %0, %1;" \
        :: "r"(tmem_addr), "r"((uint32_t)(nCols)))

#define TCGEN05_RELINQUISH_CG2() \
    asm volatile("tcgen05.relinquish_alloc_permit.cta_group::2.sync.aligned;")

#define TCGEN05_COMMIT_MC_CG2(mbar_smem_addr, mask) \
    asm volatile("tcgen05.commit.cta_group::2.mbarrier::arrive::one.shared::cluster.multicast::cluster.b64 [%0], %1;" \
        :: "r"((uint32_t)(mbar_smem_addr)), "h"((uint16_t)(mask)) : "memory")

#define TCGEN05_WAIT_LD() \
    asm volatile("tcgen05.wait::ld.sync.aligned;" ::: "memory")

#define TCGEN05_FENCE_BEFORE() \
    asm volatile("tcgen05.fence::before_thread_sync;" ::: "memory")

#define TCGEN05_FENCE_AFTER() \
    asm volatile("tcgen05.fence::after_thread_sync;" ::: "memory")

#define TCGEN05_LD_32X32B_X32(r, tmem_addr) \
    asm volatile( \
        "tcgen05.ld.sync.aligned.32x32b.x32.b32 " \
        "{%0, %1, %2, %3, %4, %5, %6, %7, " \
        " %8, %9, %10, %11, %12, %13, %14, %15, " \
        " %16, %17, %18, %19, %20, %21, %22, %23, " \
        " %24, %25, %26, %27, %28, %29, %30, %31}, [%32];" \
        : "=r"((r)[0]),  "=r"((r)[1]),  "=r"((r)[2]),  "=r"((r)[3]), \
          "=r"((r)[4]),  "=r"((r)[5]),  "=r"((r)[6]),  "=r"((r)[7]), \
          "=r"((r)[8]),  "=r"((r)[9]),  "=r"((r)[10]), "=r"((r)[11]), \
          "=r"((r)[12]), "=r"((r)[13]), "=r"((r)[14]), "=r"((r)[15]), \
          "=r"((r)[16]), "=r"((r)[17]), "=r"((r)[18]), "=r"((r)[19]), \
          "=r"((r)[20]), "=r"((r)[21]), "=r"((r)[22]), "=r"((r)[23]), \
          "=r"((r)[24]), "=r"((r)[25]), "=r"((r)[26]), "=r"((r)[27]), \
          "=r"((r)[28]), "=r"((r)[29]), "=r"((r)[30]), "=r"((r)[31]) \
        : "r"(tmem_addr))

// SW128 K-major descriptor (LBO=1, SBO=64, version=1, layout=SW128) — validated.
static constexpr unsigned long long SMEM_DESC_BASE_SW128 =
    (2ull << 61) | (1ull << 46) | (64ull << 32) | (1ull << 16);

__device__ __forceinline__ uint64_t make_desc(uint32_t smem_addr) {
    return SMEM_DESC_BASE_SW128 | ((uint64_t)(smem_addr >> 4) & 0x3FFFull);
}

#if HAS_TCGEN05
// cg2 bf16 SS MMA (8 zero regs for disable-output-lane, per the cg2 example).
__device__ __forceinline__ void mma_bf16_ss_cg2(uint32_t d_tmem, uint64_t a_desc,
                                                uint64_t b_desc, uint32_t idesc,
                                                uint32_t enable_d) {
    asm volatile(
        "{\n\t.reg .pred p;\n\t"
        "setp.ne.u32 p, %5, 0;\n\t"
        "tcgen05.mma.cta_group::2.kind::f16 [%0], %1, %2, %3, "
        "{%4, %4, %4, %4, %4, %4, %4, %4}, p;\n\t}"
        :: "r"(d_tmem), "l"(a_desc), "l"(b_desc), "r"(idesc), "r"(0u), "r"(enable_d)
        : "memory");
}

__device__ __forceinline__ void tma_ld2(uint32_t smem_addr, const CUtensorMap* tmap,
                                        int cx, int cy, uint32_t mbar) {
    asm volatile(
        "cp.async.bulk.tensor.2d.shared::cta.global.tile.mbarrier::complete_tx::bytes "
        "[%0], [%1, {%2, %3}], [%4];"
        :: "r"(smem_addr), "l"(tmap), "r"(cx), "r"(cy), "r"(mbar) : "memory");
}
#endif

// ---------------------------------------------------------------------------
// Fallback helpers: ldmatrix + int8 mma.sync (family-portable)
// ---------------------------------------------------------------------------
__device__ __forceinline__ void ldsm_x4(uint32_t& r0, uint32_t& r1,
                                        uint32_t& r2, uint32_t& r3, uint32_t addr) {
    asm volatile("ldmatrix.sync.aligned.m8n8.x4.shared.b16 {%0,%1,%2,%3}, [%4];"
                 : "=r"(r0), "=r"(r1), "=r"(r2), "=r"(r3) : "r"(addr));
}

__device__ __forceinline__ void imma16832(int* c, const uint32_t* a, const uint32_t* b) {
    asm volatile(
        "mma.sync.aligned.m16n8k32.row.col.s32.s8.s8.s32 "
        "{%0,%1,%2,%3}, {%4,%5,%6,%7}, {%8,%9}, {%0,%1,%2,%3};"
        : "+r"(c[0]), "+r"(c[1]), "+r"(c[2]), "+r"(c[3])
        : "r"(a[0]), "r"(a[1]), "r"(a[2]), "r"(a[3]), "r"(b[0]), "r"(b[1]));
}

// ---------------------------------------------------------------------------
// Pre-pass: int32 -> bf16 (tcgen05 path) or int8 (fallback path)
// ---------------------------------------------------------------------------
__global__ void cvt_kernel(const int4* __restrict__ in, void* __restrict__ out, int n4) {
    int i = blockIdx.x * blockDim.x + threadIdx.x;
    if (i >= n4) return;
    int4 v = in[i];
#if HAS_TCGEN05
    __nv_bfloat162 p0, p1;
    p0.x = __int2bfloat16_rn(v.x); p0.y = __int2bfloat16_rn(v.y);
    p1.x = __int2bfloat16_rn(v.z); p1.y = __int2bfloat16_rn(v.w);
    uint2 o;
    o.x = *reinterpret_cast<unsigned*>(&p0);
    o.y = *reinterpret_cast<unsigned*>(&p1);
    reinterpret_cast<uint2*>(out)[i] = o;
#else
    char4 o;
    o.x = (char)v.x; o.y = (char)v.y; o.z = (char)v.z; o.w = (char)v.w;
    reinterpret_cast<char4*>(out)[i] = o;
#endif
}

// ---------------------------------------------------------------------------
// GEMM: cg2 pair computes 256x512 (48B L2 traffic per output).
// WARP-SPECIALIZED: warp 0 = TMA producer, warp 1 = MMA driver / PRDY
// forwarder. Wait latencies no longer serialize on one instruction stream
// (R12 lesson: the single-thread driver loop was the limiter).
// ---------------------------------------------------------------------------
__global__ void __launch_bounds__(GTHREADS) __cluster_dims__(CLUSTER, 1, 1)
q8gemm_kernel(
    const __grid_constant__ CUtensorMap tmA,
    const __grid_constant__ CUtensorMap tmB,
    const float* __restrict__ bias,
    const float* __restrict__ xsc,
    const float* __restrict__ wsc,
    float* __restrict__ out)
{
    extern __shared__ __align__(1024) char smem[];
    const int tid = threadIdx.x;
    const int wid = tid >> 5;
    const int lid = tid & 31;

    // Pair rasterization: 32 m-pairs x 32 n-tiles; 8-n-tile bands keep a 32MB
    // B band L2-resident.
    const int rank = blockIdx.x & 1;             // == cluster rank (dim x = 2)
    const int pair = blockIdx.x >> 1;            // 0..1023
    const int band = pair / (8 * 32);
    const int r    = pair % (8 * 32);
    const int mtp  = r / 8;
    const int nt   = band * 8 + (r % 8);
    const int m0c  = mtp * TILE_MP + rank * 128; // this CTA's 128 rows
    const int n0   = nt * TILE_NP;               // 512-wide N tile

#if HAS_TCGEN05
    // ======================= tcgen05 cg2 bf16 path =======================
    const uint32_t sb = smem_u32(smem);

    if (wid == 0) TCGEN05_ALLOC_CG2(sb + SM_TMEMPTR, 512);
    if (tid == 0) {
        #pragma unroll
        for (int s = 0; s < NSTAGE; s++) {
            MBARRIER_INIT(sb + SM_FULL(s), 1);   // local expect_tx arrive
            MBARRIER_INIT(sb + SM_DONE(s), 1);   // leader's multicast commit
            MBARRIER_INIT(sb + SM_PRDY(s), 1);   // peer stage-ready (leader-side)
        }
        MBARRIER_INIT(sb + SM_FINAL, 1);
    }
    __syncthreads();
    CLUSTER_SYNC();   // peer barriers live before any cross-CTA arrive/commit

    uint32_t tbase;
    asm volatile("ld.shared.b32 %0, [%1];" : "=r"(tbase) : "r"(sb + SM_TMEMPTR));

    if (wid == 0) {
        // ============ producer warp (both ranks): prologue + refills ============
        if (elect_one_pred()) {
            #pragma unroll
            for (int s = 0; s < NSTAGE; s++) {
                MBARRIER_EXPECT_TX(sb + SM_FULL(s), STAGE_BYTES);
                tma_ld2(sb + SM_A(s),           &tmA, s * KC, m0c,                   sb + SM_FULL(s));
                tma_ld2(sb + SM_B(s),           &tmB, s * KC, n0 + rank * 128,       sb + SM_FULL(s));
                tma_ld2(sb + SM_B(s) + B_CHUNK, &tmB, s * KC, n0 + 256 + rank * 128, sb + SM_FULL(s));
            }
            for (int kk = NSTAGE; kk < NKI; kk++) {
                const int rs  = kk - NSTAGE;          // generation being replaced
                const int st  = rs & (NSTAGE - 1);
                MBARRIER_WAIT_PARITY(sb + SM_DONE(st), (rs >> 2) & 1);
                MBARRIER_EXPECT_TX(sb + SM_FULL(st), STAGE_BYTES);
                tma_ld2(sb + SM_A(st),           &tmA, kk * KC, m0c,                   sb + SM_FULL(st));
                tma_ld2(sb + SM_B(st),           &tmB, kk * KC, n0 + rank * 128,       sb + SM_FULL(st));
                tma_ld2(sb + SM_B(st) + B_CHUNK, &tmB, kk * KC, n0 + 256 + rank * 128, sb + SM_FULL(st));
            }
        }
    } else if (wid == 1) {
        // ============ control warp: MMA driver (leader) / forwarder (peer) ======
        if (rank == 0) {
            if (elect_one_pred()) {
                for (int ks = 0; ks < NKI; ks++) {
                    const int st = ks & (NSTAGE - 1);
                    const int ph = (ks >> 2) & 1;
                    MBARRIER_WAIT_PARITY(sb + SM_FULL(st), ph);   // my slices
                    MBARRIER_WAIT_PARITY(sb + SM_PRDY(st), ph);   // peer slices
                    uint64_t ad = make_desc(sb + SM_A(st));
                    uint64_t b0 = make_desc(sb + SM_B(st));
                    uint64_t b1 = make_desc(sb + SM_B(st) + B_CHUNK);
                    #pragma unroll
                    for (int j = 0; j < 4; j++) {                 // 4 x K16 = K64
                        uint32_t e = (uint32_t)((ks | j) != 0);
                        mma_bf16_ss_cg2(tbase,       ad + j * 2, b0 + j * 2, MMA_IDESC_CG2, e);
                        mma_bf16_ss_cg2(tbase + 256, ad + j * 2, b1 + j * 2, MMA_IDESC_CG2, e);
                    }
                    TCGEN05_COMMIT_MC_CG2(sb + SM_DONE(st), 0x3);
                }
                TCGEN05_COMMIT_MC_CG2(sb + SM_FINAL, 0x3);
            }
        } else {
            if (elect_one_pred()) {
                for (int ks = 0; ks < NKI; ks++) {
                    const int st = ks & (NSTAGE - 1);
                    const int ph = (ks >> 2) & 1;
                    MBARRIER_WAIT_PARITY(sb + SM_FULL(st), ph);   // my TMAs landed
                    MBARRIER_ARRIVE_CLUSTER(sb + SM_PRDY(st), 0); // tell leader
                }
            }
        }
    }

    // Epilogue: each CTA reads its own 128 rows x 512 cols from TMEM.
    MBARRIER_WAIT_PARITY(sb + SM_FINAL, 0);
    TCGEN05_FENCE_AFTER();

    float* s_ws = reinterpret_cast<float*>(smem + SM_TILES);   // stage area is dead
    float* s_bi = s_ws + TILE_NP;
    for (int i = tid; i < TILE_NP; i += GTHREADS) {
        s_ws[i] = wsc[n0 + i];
        s_bi[i] = bias[n0 + i];
    }
    __syncthreads();

    const int row = m0c + wid * 32 + lid;
    const float xsv = xsc[row];
    float* orow = out + (size_t)row * OUT_F + n0;

    #pragma unroll 1
    for (int cb = 0; cb < TILE_NP / 32; cb++) {    // 16 column blocks
        uint32_t rg[32];
        TCGEN05_LD_32X32B_X32(rg, tbase + cb * 32);
        TCGEN05_WAIT_LD();
        #pragma unroll
        for (int q = 0; q < 8; q++) {
            const int c = cb * 32 + q * 4;
            float4 v;
            v.x = fmaf(__uint_as_float(rg[q * 4 + 0]), xsv * s_ws[c + 0], s_bi[c + 0]);
            v.y = fmaf(__uint_as_float(rg[q * 4 + 1]), xsv * s_ws[c + 1], s_bi[c + 1]);
            v.z = fmaf(__uint_as_float(rg[q * 4 + 2]), xsv * s_ws[c + 2], s_bi[c + 2]);
            v.w = fmaf(__uint_as_float(rg[q * 4 + 3]), xsv * s_ws[c + 3], s_bi[c + 3]);
            *reinterpret_cast<float4*>(orow + c) = v;
        }
    }
    TCGEN05_FENCE_BEFORE();
    __syncthreads();
    if (wid == 0) {
        TCGEN05_RELINQUISH_CG2();
        TCGEN05_DEALLOC_CG2(tbase, 512);
    }
    CLUSTER_SYNC();   // no CTA exits while peer traffic may be in flight

#else
    // =================== portable int8 mma.sync fallback ===================
    // Each CTA computes its 128 rows x 512 cols independently.
    const int8_t* x8 = reinterpret_cast<const int8_t*>(g_xb);
    const int8_t* w8 = reinterpret_cast<const int8_t*>(g_wb);

    const int AST = 80, BST = 80;
    char* sA = smem;
    char* sB = smem + 128 * AST;
    const uint32_t sAu = smem_u32(sA);
    const uint32_t sBu = smem_u32(sB);
    const int warp_row = wid * 32;

    for (int nc = 0; nc < 8; nc++) {               // 8 x 64-col chunks of 512
        const int nb = n0 + nc * 64;
        int acc[2][8][4];
        #pragma unroll
        for (int a = 0; a < 2; a++)
            #pragma unroll
            for (int b = 0; b < 8; b++)
                #pragma unroll
                for (int c = 0; c < 4; c++) acc[a][b][c] = 0;

        for (int kt = 0; kt < 64; kt++) {
            const int k0 = kt * 64;
            __syncthreads();
            {
                const uint4* src = reinterpret_cast<const uint4*>(
                    x8 + (size_t)(m0c + tid) * IN_F + k0);
                uint4* dst = reinterpret_cast<uint4*>(sA + tid * AST);
                #pragma unroll
                for (int j = 0; j < 4; j++) dst[j] = src[j];
            }
            {
                const int br = tid >> 1, hh = tid & 1;
                const uint4* src = reinterpret_cast<const uint4*>(
                    w8 + (size_t)(nb + br) * IN_F + k0 + hh * 32);
                uint4* dst = reinterpret_cast<uint4*>(sB + br * BST + hh * 32);
                dst[0] = src[0]; dst[1] = src[1];
            }
            __syncthreads();

            #pragma unroll
            for (int s = 0; s < 2; s++) {
                uint32_t afr[2][4];
                #pragma unroll
                for (int mt2 = 0; mt2 < 2; mt2++) {
                    uint32_t addr = sAu +
                        (uint32_t)(warp_row + mt2 * 16 + (lid & 15)) * AST +
                        s * 32 + ((lid >= 16) ? 16 : 0);
                    ldsm_x4(afr[mt2][0], afr[mt2][1], afr[mt2][2], afr[mt2][3], addr);
                }
                uint32_t bfr[4][4];
                #pragma unroll
                for (int p = 0; p < 4; p++) {
                    uint32_t addr = sBu +
                        (uint32_t)(p * 16 + (lid & 7) + ((lid >= 16) ? 8 : 0)) * BST +
                        s * 32 + ((lid & 8) ? 16 : 0);
                    ldsm_x4(bfr[p][0], bfr[p][1], bfr[p][2], bfr[p][3], addr);
                }
                #pragma unroll
                for (int mt2 = 0; mt2 < 2; mt2++)
                    #pragma unroll
                    for (int nt2 = 0; nt2 < 8; nt2++) {
                        uint32_t bb[2];
                        bb[0] = bfr[nt2 >> 1][(nt2 & 1) ? 2 : 0];
                        bb[1] = bfr[nt2 >> 1][(nt2 & 1) ? 3 : 1];
                        imma16832(acc[mt2][nt2], afr[mt2], bb);
                    }
            }
        }
        #pragma unroll
        for (int mt2 = 0; mt2 < 2; mt2++) {
            const int r0_ = m0c + warp_row + mt2 * 16 + (lid >> 2);
            const float xs0 = xsc[r0_], xs1 = xsc[r0_ + 8];
            #pragma unroll
            for (int nt2 = 0; nt2 < 8; nt2++) {
                const int c0 = nb + nt2 * 8 + (lid & 3) * 2;
                const float w0 = wsc[c0], w1 = wsc[c0 + 1];
                const float b0 = bias[c0], b1 = bias[c0 + 1];
                float* o0 = out + (size_t)r0_ * OUT_F + c0;
                float* o1 = out + (size_t)(r0_ + 8) * OUT_F + c0;
                o0[0] = fmaf((float)acc[mt2][nt2][0], xs0 * w0, b0);
                o0[1] = fmaf((float)acc[mt2][nt2][1], xs0 * w1, b1);
                o1[0] = fmaf((float)acc[mt2][nt2][2], xs1 * w0, b0);
                o1[1] = fmaf((float)acc[mt2][nt2][3], xs1 * w1, b1);
            }
        }
    }
#endif
}

// ---------------------------------------------------------------------------
// Host launcher
// ---------------------------------------------------------------------------
typedef CUresult (*tmencode_fn_t)(
    CUtensorMap*, CUtensorMapDataType, cuuint32_t, void*,
    const cuuint64_t*, const cuuint64_t*, const cuuint32_t*, const cuuint32_t*,
    CUtensorMapInterleave, CUtensorMapSwizzle, CUtensorMapL2promotion,
    CUtensorMapFloatOOBfill);

extern "C" void kernel_launch(void* const* d_in, const int* in_sizes, int n_in,
                              void* d_out, int out_size) {
    const int*   x    = (const int*)d_in[0];
    const int*   w    = (const int*)d_in[1];
    const float* bias = (const float*)d_in[2];
    const float* xsc  = (const float*)d_in[3];
    const float* wsc  = (const float*)d_in[4];
    float* out = (float*)d_out;

    void* xb_ptr = nullptr;
    void* wb_ptr = nullptr;
    cudaGetSymbolAddress(&xb_ptr, g_xb);
    cudaGetSymbolAddress(&wb_ptr, g_wb);

    // Pre-pass: int32 -> (bf16 | int8), matching whichever GEMM variant loads.
    {
        int n4x = TOKENS * IN_F / 4;
        int n4w = OUT_F * IN_F / 4;
        cvt_kernel<<<(n4x + 255) / 256, 256>>>((const int4*)x, xb_ptr, n4x);
        cvt_kernel<<<(n4w + 255) / 256, 256>>>((const int4*)w, wb_ptr, n4w);
    }

    // TMA descriptors: SW128, 128B inner rows, 128-row boxes (A half / B chunk).
    tmencode_fn_t enc = nullptr;
    {
        void* fn = nullptr;
        cudaDriverEntryPointQueryResult qres;
#if CUDART_VERSION >= 12050
        cudaGetDriverEntryPointByVersion("cuTensorMapEncodeTiled", &fn, 12000,
                                         cudaEnableDefault, &qres);
#else
        cudaGetDriverEntryPoint("cuTensorMapEncodeTiled", &fn,
                                cudaEnableDefault, &qres);
#endif
        enc = (tmencode_fn_t)fn;
    }

    alignas(64) CUtensorMap tmA, tmB;
    if (enc) {
        {
            cuuint64_t dims[2] = {IN_F, TOKENS};
            cuuint64_t strd[1] = {IN_F * 2ull};
            cuuint32_t box[2]  = {KC, 128};             // 64 bf16 = 128B inner
            cuuint32_t es[2]   = {1, 1};
            enc(&tmA, CU_TENSOR_MAP_DATA_TYPE_BFLOAT16, 2, xb_ptr, dims, strd, box, es,
                CU_TENSOR_MAP_INTERLEAVE_NONE, CU_TENSOR_MAP_SWIZZLE_128B,
                CU_TENSOR_MAP_L2_PROMOTION_L2_128B, CU_TENSOR_MAP_FLOAT_OOB_FILL_NONE);
        }
        {
            cuuint64_t dims[2] = {IN_F, OUT_F};
            cuuint64_t strd[1] = {IN_F * 2ull};
            cuuint32_t box[2]  = {KC, 128};
            cuuint32_t es[2]   = {1, 1};
            enc(&tmB, CU_TENSOR_MAP_DATA_TYPE_BFLOAT16, 2, wb_ptr, dims, strd, box, es,
                CU_TENSOR_MAP_INTERLEAVE_NONE, CU_TENSOR_MAP_SWIZZLE_128B,
                CU_TENSOR_MAP_L2_PROMOTION_L2_128B, CU_TENSOR_MAP_FLOAT_OOB_FILL_NONE);
        }
    }

    cudaFuncSetAttribute(q8gemm_kernel,
                         cudaFuncAttributeMaxDynamicSharedMemorySize, SMEM_TOTAL);

    const int grid = (TOKENS / TILE_MP) * (OUT_F / TILE_NP) * CLUSTER;  // 2048
    q8gemm_kernel<<<grid, GTHREADS, SMEM_TOTAL>>>(tmA, tmB, bias, xsc, wsc, out);
}

// round 14
// speedup vs baseline: 1.0734x; 1.0650x over previous
#include <cuda_runtime.h>
#include <cuda.h>
#include <cuda_bf16.h>
#include <cstdint>

// ---------------------------------------------------------------------------
// Problem constants
// ---------------------------------------------------------------------------
#define TOKENS 8192
#define IN_F   4096
#define OUT_F  16384

#define TILE_MP 256                  // M per cluster pair (128 per CTA)
#define TILE_NP 512                  // N per cluster pair (2 x N=256 MMAs)
#define GTHREADS 256                 // w0=producer, w1=control, w4-7=epilogue
#define CLUSTER 2
#define NT_TOTAL 1024                // 32 m-pairs x 32 n-tiles

// SW128 atoms: 64 bf16 per stage-row (128B rows) — validated R5/R10/R13
#define KC     64
#define NKI    (IN_F / KC)           // 64 K-iterations per tile
#define NSTAGE 4                     // ring over a GLOBAL generation counter

// Per-CTA stage: A 128x128B (16KB) + B 2x128x128B (32KB) = 48KB
#define SM_TMEMPTR 0
#define SM_FULL(s)  (64  + (s) * 8)
#define SM_DONE(s)  (192 + (s) * 8)
#define SM_PRDY(s)  (320 + (s) * 8)
#define SM_FINAL    448
#define SM_EPIFREE  456
#define SM_TILES    1024
#define A_BYTES     (128 * KC * 2)            // 16384
#define B_CHUNK     (128 * KC * 2)            // 16384
#define STAGE_BYTES (A_BYTES + 2 * B_CHUNK)   // 49152
#define SM_A(s) (SM_TILES + (s) * STAGE_BYTES)
#define SM_B(s) (SM_A(s) + A_BYTES)
#define SM_SCALES  (SM_TILES + NSTAGE * STAGE_BYTES)     // 197632
#define SMEM_TOTAL (SM_SCALES + 2 * TILE_NP * 4)          // 201728 (1 CTA/SM)

// Arch-specific feature gate: tcgen05 legal only on sm_100a / sm_103a targets.
#if defined(__CUDA_ARCH_FEAT_SM103_ALL) || defined(__CUDA_ARCH_FEAT_SM100_ALL)
#define HAS_TCGEN05 1
#else
#define HAS_TCGEN05 0
#endif

// idesc, kind::f16 cg2: dtype=F32, a=BF16, b=BF16, N=256, M_TOTAL=256.
// (Validated R11-R13: passed, rel_err 5.7e-8.)
static constexpr uint32_t MMA_IDESC_CG2 =
    (1u << 4) | (1u << 7) | (1u << 10) | ((256u / 8u) << 17) | ((256u / 16u) << 24);

// Scratch (device-global scratch is the sanctioned no-alloc path).
__device__ __nv_bfloat16 g_xb[(size_t)TOKENS * IN_F];   // 64 MB
__device__ __nv_bfloat16 g_wb[(size_t)OUT_F * IN_F];    // 128 MB

// ---------------------------------------------------------------------------
// Common PTX helpers
// ---------------------------------------------------------------------------
__device__ __forceinline__ uint32_t elect_one_pred() {
    uint32_t pred;
    asm volatile(
        "{\n\t.reg .pred p;\n\telect.sync _|p, 0xFFFFFFFF;\n\t"
        "selp.b32 %0, 1, 0, p;\n\t}" : "=r"(pred));
    return pred;
}

__device__ __forceinline__ uint32_t smem_u32(const void* p) {
    uint32_t a;
    asm("{ .reg .u64 t; cvta.to.shared.u64 t, %1; cvt.u32.u64 %0, t; }"
        : "=r"(a) : "l"(p));
    return a;
}

#define MBARRIER_INIT(addr, cnt) \
    asm volatile("mbarrier.init.shared.b64 [%0], %1;" :: "r"((uint32_t)(addr)), "r"((uint32_t)(cnt)) : "memory")

#define MBARRIER_EXPECT_TX(addr, tx) \
    asm volatile("mbarrier.arrive.expect_tx.shared.b64 _, [%0], %1;" :: "r"((uint32_t)(addr)), "r"((uint32_t)(tx)) : "memory")

// Arrive on the mbarrier at the same SMEM offset in cluster CTA `rank`.
#define MBARRIER_ARRIVE_CLUSTER(local_mbar_addr, target_rank) \
    asm volatile( \
        "{\n\t.reg .b32 remAddr32;\n\t" \
        "mapa.shared::cluster.u32 remAddr32, %0, %1;\n\t" \
        "mbarrier.arrive.shared::cluster.b64 _, [remAddr32];\n\t}" \
        :: "r"((uint32_t)(local_mbar_addr)), "r"((uint32_t)(target_rank)) : "memory")

#define MBARRIER_WAIT_PARITY(mbar_smem_addr, phase_parity) do { \
    uint32_t _mbar = (uint32_t)(mbar_smem_addr); \
    uint32_t _parity = (uint32_t)(phase_parity); \
    uint32_t _done_; \
    asm volatile( \
        "{\n\t.reg .pred p;\n\t" \
        "mbarrier.try_wait.parity.acquire.cta.shared::cta.b64 p, [%1], %2;\n\t" \
        "selp.b32 %0, 1, 0, p;\n\t}" \
        : "=r"(_done_) : "r"(_mbar), "r"(_parity) : "memory"); \
    if (!_done_) { \
        asm volatile( \
            "{\n\t.reg .pred P1;\n\t" \
            "WAIT_LOOP_%=:\n\t" \
            "mbarrier.try_wait.parity.acquire.cta.shared::cta.b64 P1, [%0], %1, 0x989680;\n\t" \
            "@P1 bra.uni WAIT_DONE_%=;\n\t" \
            "bra.uni WAIT_LOOP_%=;\n\t" \
            "WAIT_DONE_%=:\n\t}" \
            :: "r"(_mbar), "r"(_parity) : "memory"); \
    } \
} while (0)

#define CLUSTER_SYNC() do { \
    asm volatile("barrier.cluster.arrive.aligned;" ::: "memory"); \
    asm volatile("barrier.cluster.wait.aligned;"   ::: "memory"); \
} while (0)

#define NAMED_BAR_EPI() asm volatile("bar.sync 1, 128;" ::: "memory")

// ---------------------------------------------------------------------------
// tcgen05 cg2 macros (only EXPANDED inside HAS_TCGEN05 regions)
// ---------------------------------------------------------------------------
#define TCGEN05_ALLOC_CG2(smem_result_addr, nCols) \
    asm volatile("tcgen05.alloc.cta_group::2.sync.aligned.shared::cta.b32 [%0], %1;" \
        :: "r"((uint32_t)(smem_result_addr)), "r"((uint32_t)(nCols)) : "memory")

#define TCGEN05_DEALLOC_CG2(tmem_addr, nCols) \
    asm volatile("tcgen05.dealloc.cta_group::2.sync.aligned.b32 %0, %1;" \
        :: "r"(tmem_addr), "r"((uint32_t)(nCols)))

#define TCGEN05_RELINQUISH_CG2() \
    asm volatile("tcgen05.relinquish_alloc_permit.cta_group::2.sync.aligned;")

#define TCGEN05_COMMIT_MC_CG2(mbar_smem_addr, mask) \
    asm volatile("tcgen05.commit.cta_group::2.mbarrier::arrive::one.shared::cluster.multicast::cluster.b64 [%0], %1;" \
        :: "r"((uint32_t)(mbar_smem_addr)), "h"((uint16_t)(mask)) : "memory")

#define TCGEN05_WAIT_LD() \
    asm volatile("tcgen05.wait::ld.sync.aligned;" ::: "memory")

#define TCGEN05_FENCE_BEFORE() \
    asm volatile("tcgen05.fence::before_thread_sync;" ::: "memory")

#define TCGEN05_FENCE_AFTER() \
    asm volatile("tcgen05.fence::after_thread_sync;" ::: "memory")

#define TCGEN05_LD_32X32B_X32(r, tmem_addr) \
    asm volatile( \
        "tcgen05.ld.sync.aligned.32x32b.x32.b32 " \
        "{%0, %1, %2, %3, %4, %5, %6, %7, " \
        " %8, %9, %10, %11, %12, %13, %14, %15, " \
        " %16, %17, %18, %19, %20, %21, %22, %23, " \
        " %24, %25, %26, %27, %28, %29, %30, %31}, [%32];" \
        : "=r"((r)[0]),  "=r"((r)[1]),  "=r"((r)[2]),  "=r"((r)[3]), \
          "=r"((r)[4]),  "=r"((r)[5]),  "=r"((r)[6]),  "=r"((r)[7]), \
          "=r"((r)[8]),  "=r"((r)[9]),  "=r"((r)[10]), "=r"((r)[11]), \
          "=r"((r)[12]), "=r"((r)[13]), "=r"((r)[14]), "=r"((r)[15]), \
          "=r"((r)[16]), "=r"((r)[17]), "=r"((r)[18]), "=r"((r)[19]), \
          "=r"((r)[20]), "=r"((r)[21]), "=r"((r)[22]), "=r"((r)[23]), \
          "=r"((r)[24]), "=r"((r)[25]), "=r"((r)[26]), "=r"((r)[27]), \
          "=r"((r)[28]), "=r"((r)[29]), "=r"((r)[30]), "=r"((r)[31]) \
        : "r"(tmem_addr))

// SW128 K-major descriptor (LBO=1, SBO=64, version=1, layout=SW128) — validated.
static constexpr unsigned long long SMEM_DESC_BASE_SW128 =
    (2ull << 61) | (1ull << 46) | (64ull << 32) | (1ull << 16);

__device__ __forceinline__ uint64_t make_desc(uint32_t smem_addr) {
    return SMEM_DESC_BASE_SW128 | ((uint64_t)(smem_addr >> 4) & 0x3FFFull);
}

// Band-local tile mapping (identical raster to R13: 8-n-tile bands).
__device__ __forceinline__ void tile_coords(int t, int rank, int& m0c, int& n0) {
    const int band = t >> 8;           // 256 tiles per band
    const int r    = t & 255;
    const int mtp  = r >> 3;
    const int nt   = (band << 3) + (r & 7);
    m0c = mtp * TILE_MP + rank * 128;
    n0  = nt * TILE_NP;
}

#if HAS_TCGEN05
// cg2 bf16 SS MMA (8 zero regs for disable-output-lane, per the cg2 example).
__device__ __forceinline__ void mma_bf16_ss_cg2(uint32_t d_tmem, uint64_t a_desc,
                                                uint64_t b_desc, uint32_t idesc,
                                                uint32_t enable_d) {
    asm volatile(
        "{\n\t.reg .pred p;\n\t"
        "setp.ne.u32 p, %5, 0;\n\t"
        "tcgen05.mma.cta_group::2.kind::f16 [%0], %1, %2, %3, "
        "{%4, %4, %4, %4, %4, %4, %4, %4}, p;\n\t}"
        :: "r"(d_tmem), "l"(a_desc), "l"(b_desc), "r"(idesc), "r"(0u), "r"(enable_d)
        : "memory");
}

__device__ __forceinline__ void tma_ld2(uint32_t smem_addr, const CUtensorMap* tmap,
                                        int cx, int cy, uint32_t mbar) {
    asm volatile(
        "cp.async.bulk.tensor.2d.shared::cta.global.tile.mbarrier::complete_tx::bytes "
        "[%0], [%1, {%2, %3}], [%4];"
        :: "r"(smem_addr), "l"(tmap), "r"(cx), "r"(cy), "r"(mbar) : "memory");
}
#endif

// ---------------------------------------------------------------------------
// Fallback helpers: ldmatrix + int8 mma.sync (family-portable)
// ---------------------------------------------------------------------------
__device__ __forceinline__ void ldsm_x4(uint32_t& r0, uint32_t& r1,
                                        uint32_t& r2, uint32_t& r3, uint32_t addr) {
    asm volatile("ldmatrix.sync.aligned.m8n8.x4.shared.b16 {%0,%1,%2,%3}, [%4];"
                 : "=r"(r0), "=r"(r1), "=r"(r2), "=r"(r3) : "r"(addr));
}

__device__ __forceinline__ void imma16832(int* c, const uint32_t* a, const uint32_t* b) {
    asm volatile(
        "mma.sync.aligned.m16n8k32.row.col.s32.s8.s8.s32 "
        "{%0,%1,%2,%3}, {%4,%5,%6,%7}, {%8,%9}, {%0,%1,%2,%3};"
        : "+r"(c[0]), "+r"(c[1]), "+r"(c[2]), "+r"(c[3])
        : "r"(a[0]), "r"(a[1]), "r"(a[2]), "r"(a[3]), "r"(b[0]), "r"(b[1]));
}

// ---------------------------------------------------------------------------
// Pre-pass: int32 -> bf16 (tcgen05 path) or int8 (fallback path)
// ---------------------------------------------------------------------------
__global__ void cvt_kernel(const int4* __restrict__ in, void* __restrict__ out, int n4) {
    int i = blockIdx.x * blockDim.x + threadIdx.x;
    if (i >= n4) return;
    int4 v = in[i];
#if HAS_TCGEN05
    __nv_bfloat162 p0, p1;
    p0.x = __int2bfloat16_rn(v.x); p0.y = __int2bfloat16_rn(v.y);
    p1.x = __int2bfloat16_rn(v.z); p1.y = __int2bfloat16_rn(v.w);
    uint2 o;
    o.x = *reinterpret_cast<unsigned*>(&p0);
    o.y = *reinterpret_cast<unsigned*>(&p1);
    reinterpret_cast<uint2*>(out)[i] = o;
#else
    char4 o;
    o.x = (char)v.x; o.y = (char)v.y; o.z = (char)v.z; o.w = (char)v.w;
    reinterpret_cast<char4*>(out)[i] = o;
#endif
}

// ---------------------------------------------------------------------------
// PERSISTENT GEMM: each cg2 pair loops over ~NT_TOTAL/nslots tiles.
// w0 = continuous TMA producer (global generation ring, prefetches across
// tile boundaries during epilogues); w1 = MMA driver (leader) / PRDY
// forwarder (peer); w4-7 = per-tile epilogue, gating next tile's MMAs via
// EPI_FREE (count 2, cluster-scope, tile-granularity only).
// ---------------------------------------------------------------------------
__global__ void __launch_bounds__(GTHREADS) __cluster_dims__(CLUSTER, 1, 1)
q8gemm_kernel(
    const __grid_constant__ CUtensorMap tmA,
    const __grid_constant__ CUtensorMap tmB,
    const float* __restrict__ bias,
    const float* __restrict__ xsc,
    const float* __restrict__ wsc,
    float* __restrict__ out,
    int nslots)
{
    extern __shared__ __align__(1024) char smem[];
    const int tid  = threadIdx.x;
    const int wid  = tid >> 5;
    const int lid  = tid & 31;
    const int rank = blockIdx.x & 1;             // cluster rank
    const int slot = blockIdx.x >> 1;            // persistent pair slot

#if HAS_TCGEN05
    const uint32_t sb = smem_u32(smem);

    if (wid == 0) TCGEN05_ALLOC_CG2(sb + SM_TMEMPTR, 512);
    if (tid == 0) {
        #pragma unroll
        for (int s = 0; s < NSTAGE; s++) {
            MBARRIER_INIT(sb + SM_FULL(s), 1);
            MBARRIER_INIT(sb + SM_DONE(s), 1);
            MBARRIER_INIT(sb + SM_PRDY(s), 1);
        }
        MBARRIER_INIT(sb + SM_FINAL, 1);
        MBARRIER_INIT(sb + SM_EPIFREE, 2);   // one arrive per CTA's epilogue
    }
    __syncthreads();
    CLUSTER_SYNC();

    uint32_t tbase;
    asm volatile("ld.shared.b32 %0, [%1];" : "=r"(tbase) : "r"(sb + SM_TMEMPTR));

    if (wid == 0) {
        // ================= producer: one continuous TMA stream =================
        if (elect_one_pred()) {
            int g = 0;
            for (int t = slot; t < NT_TOTAL; t += nslots) {
                int m0c, n0; tile_coords(t, rank, m0c, n0);
                for (int ks = 0; ks < NKI; ks++, g++) {
                    const int s = g & (NSTAGE - 1);
                    if (g >= NSTAGE)
                        MBARRIER_WAIT_PARITY(sb + SM_DONE(s), ((g - NSTAGE) >> 2) & 1);
                    MBARRIER_EXPECT_TX(sb + SM_FULL(s), STAGE_BYTES);
                    tma_ld2(sb + SM_A(s),           &tmA, ks * KC, m0c,                   sb + SM_FULL(s));
                    tma_ld2(sb + SM_B(s),           &tmB, ks * KC, n0 + rank * 128,       sb + SM_FULL(s));
                    tma_ld2(sb + SM_B(s) + B_CHUNK, &tmB, ks * KC, n0 + 256 + rank * 128, sb + SM_FULL(s));
                }
            }
        }
    } else if (wid == 1) {
        // ============== control: MMA driver (leader) / forwarder (peer) =========
        if (rank == 0) {
            if (elect_one_pred()) {
                int g = 0, ti = 0;
                for (int t = slot; t < NT_TOTAL; t += nslots, ti++) {
                    if (ti >= 1) {                       // TMEM free after prev epilogue
                        MBARRIER_WAIT_PARITY(sb + SM_EPIFREE, (ti - 1) & 1);
                        TCGEN05_FENCE_AFTER();
                    }
                    for (int ks = 0; ks < NKI; ks++, g++) {
                        const int s  = g & (NSTAGE - 1);
                        const int ph = (g >> 2) & 1;
                        MBARRIER_WAIT_PARITY(sb + SM_FULL(s), ph);
                        MBARRIER_WAIT_PARITY(sb + SM_PRDY(s), ph);
                        uint64_t ad = make_desc(sb + SM_A(s));
                        uint64_t b0 = make_desc(sb + SM_B(s));
                        uint64_t b1 = make_desc(sb + SM_B(s) + B_CHUNK);
                        #pragma unroll
                        for (int j = 0; j < 4; j++) {    // 4 x K16 = K64
                            uint32_t e = (uint32_t)((ks | j) != 0);
                            mma_bf16_ss_cg2(tbase,       ad + j * 2, b0 + j * 2, MMA_IDESC_CG2, e);
                            mma_bf16_ss_cg2(tbase + 256, ad + j * 2, b1 + j * 2, MMA_IDESC_CG2, e);
                        }
                        TCGEN05_COMMIT_MC_CG2(sb + SM_DONE(s), 0x3);
                    }
                    TCGEN05_COMMIT_MC_CG2(sb + SM_FINAL, 0x3);
                }
            }
        } else {
            if (elect_one_pred()) {
                int g = 0;
                for (int t = slot; t < NT_TOTAL; t += nslots)
                    for (int ks = 0; ks < NKI; ks++, g++) {
                        const int s  = g & (NSTAGE - 1);
                        const int ph = (g >> 2) & 1;
                        MBARRIER_WAIT_PARITY(sb + SM_FULL(s), ph);
                        MBARRIER_ARRIVE_CLUSTER(sb + SM_PRDY(s), 0);
                    }
            }
        }
    } else if (wid >= 4) {
        // ======================== epilogue: warps 4-7 ==========================
        float* s_ws = reinterpret_cast<float*>(smem + SM_SCALES);
        float* s_bi = s_ws + TILE_NP;
        const int etid = tid - 128;          // 0..127
        int ti = 0;
        for (int t = slot; t < NT_TOTAL; t += nslots, ti++) {
            int m0c, n0; tile_coords(t, rank, m0c, n0);
            for (int i = etid; i < TILE_NP; i += 128) {
                s_ws[i] = wsc[n0 + i];
                s_bi[i] = bias[n0 + i];
            }
            NAMED_BAR_EPI();
            MBARRIER_WAIT_PARITY(sb + SM_FINAL, ti & 1);
            TCGEN05_FENCE_AFTER();

            const int row = m0c + (wid & 3) * 32 + lid;
            const float xsv = xsc[row];
            float* orow = out + (size_t)row * OUT_F + n0;
            #pragma unroll 1
            for (int cb = 0; cb < TILE_NP / 32; cb++) {
                uint32_t rg[32];
                TCGEN05_LD_32X32B_X32(rg, tbase + cb * 32);
                TCGEN05_WAIT_LD();
                #pragma unroll
                for (int q = 0; q < 8; q++) {
                    const int c = cb * 32 + q * 4;
                    float4 v;
                    v.x = fmaf(__uint_as_float(rg[q * 4 + 0]), xsv * s_ws[c + 0], s_bi[c + 0]);
                    v.y = fmaf(__uint_as_float(rg[q * 4 + 1]), xsv * s_ws[c + 1], s_bi[c + 1]);
                    v.z = fmaf(__uint_as_float(rg[q * 4 + 2]), xsv * s_ws[c + 2], s_bi[c + 2]);
                    v.w = fmaf(__uint_as_float(rg[q * 4 + 3]), xsv * s_ws[c + 3], s_bi[c + 3]);
                    *reinterpret_cast<float4*>(orow + c) = v;
                }
            }
            TCGEN05_FENCE_BEFORE();
            NAMED_BAR_EPI();                 // all epilogue reads (TMEM + s_ws) done
            if (wid == 4 && elect_one_pred())
                MBARRIER_ARRIVE_CLUSTER(sb + SM_EPIFREE, 0);   // to leader
        }
    }

    __syncthreads();
    if (wid == 0) {
        TCGEN05_RELINQUISH_CG2();
        TCGEN05_DEALLOC_CG2(tbase, 512);
    }
    CLUSTER_SYNC();

#else
    // =================== portable int8 mma.sync fallback ===================
    // Persistent over the same tile list; warps 0-3 compute, warps 4-7 only
    // participate in __syncthreads.
    const int8_t* x8 = reinterpret_cast<const int8_t*>(g_xb);
    const int8_t* w8 = reinterpret_cast<const int8_t*>(g_wb);

    const int AST = 80, BST = 80;
    char* sA = smem;
    char* sB = smem + 128 * AST;
    const uint32_t sAu = smem_u32(sA);
    const uint32_t sBu = smem_u32(sB);
    const int warp_row = (wid & 3) * 32;

    for (int t = slot; t < NT_TOTAL; t += nslots) {
        int m0c, n0; tile_coords(t, rank, m0c, n0);
        for (int nc = 0; nc < 8; nc++) {
            const int nb = n0 + nc * 64;
            int acc[2][8][4];
            #pragma unroll
            for (int a = 0; a < 2; a++)
                #pragma unroll
                for (int b = 0; b < 8; b++)
                    #pragma unroll
                    for (int c = 0; c < 4; c++) acc[a][b][c] = 0;

            for (int kt = 0; kt < 64; kt++) {
                const int k0 = kt * 64;
                __syncthreads();
                if (tid < 128) {
                    const uint4* src = reinterpret_cast<const uint4*>(
                        x8 + (size_t)(m0c + tid) * IN_F + k0);
                    uint4* dst = reinterpret_cast<uint4*>(sA + tid * AST);
                    #pragma unroll
                    for (int j = 0; j < 4; j++) dst[j] = src[j];
                    const int br = tid >> 1, hh = tid & 1;
                    const uint4* src2 = reinterpret_cast<const uint4*>(
                        w8 + (size_t)(nb + br) * IN_F + k0 + hh * 32);
                    uint4* dst2 = reinterpret_cast<uint4*>(sB + br * BST + hh * 32);
                    dst2[0] = src2[0]; dst2[1] = src2[1];
                }
                __syncthreads();

                if (tid < 128) {
                    #pragma unroll
                    for (int s = 0; s < 2; s++) {
                        uint32_t afr[2][4];
                        #pragma unroll
                        for (int mt2 = 0; mt2 < 2; mt2++) {
                            uint32_t addr = sAu +
                                (uint32_t)(warp_row + mt2 * 16 + (lid & 15)) * AST +
                                s * 32 + ((lid >= 16) ? 16 : 0);
                            ldsm_x4(afr[mt2][0], afr[mt2][1], afr[mt2][2], afr[mt2][3], addr);
                        }
                        uint32_t bfr[4][4];
                        #pragma unroll
                        for (int p = 0; p < 4; p++) {
                            uint32_t addr = sBu +
                                (uint32_t)(p * 16 + (lid & 7) + ((lid >= 16) ? 8 : 0)) * BST +
                                s * 32 + ((lid & 8) ? 16 : 0);
                            ldsm_x4(bfr[p][0], bfr[p][1], bfr[p][2], bfr[p][3], addr);
                        }
                        #pragma unroll
                        for (int mt2 = 0; mt2 < 2; mt2++)
                            #pragma unroll
                            for (int nt2 = 0; nt2 < 8; nt2++) {
                                uint32_t bb[2];
                                bb[0] = bfr[nt2 >> 1][(nt2 & 1) ? 2 : 0];
                                bb[1] = bfr[nt2 >> 1][(nt2 & 1) ? 3 : 1];
                                imma16832(acc[mt2][nt2], afr[mt2], bb);
                            }
                    }
                }
            }
            if (tid < 128) {
                #pragma unroll
                for (int mt2 = 0; mt2 < 2; mt2++) {
                    const int r0_ = m0c + warp_row + mt2 * 16 + (lid >> 2);
                    const float xs0 = xsc[r0_], xs1 = xsc[r0_ + 8];
                    #pragma unroll
                    for (int nt2 = 0; nt2 < 8; nt2++) {
                        const int c0 = nb + nt2 * 8 + (lid & 3) * 2;
                        const float w0 = wsc[c0], w1 = wsc[c0 + 1];
                        const float b0 = bias[c0], b1 = bias[c0 + 1];
                        float* o0 = out + (size_t)r0_ * OUT_F + c0;
                        float* o1 = out + (size_t)(r0_ + 8) * OUT_F + c0;
                        o0[0] = fmaf((float)acc[mt2][nt2][0], xs0 * w0, b0);
                        o0[1] = fmaf((float)acc[mt2][nt2][1], xs0 * w1, b1);
                        o1[0] = fmaf((float)acc[mt2][nt2][2], xs1 * w0, b0);
                        o1[1] = fmaf((float)acc[mt2][nt2][3], xs1 * w1, b1);
                    }
                }
            }
        }
    }
#endif
}

// ---------------------------------------------------------------------------
// Host launcher
// ---------------------------------------------------------------------------
typedef CUresult (*tmencode_fn_t)(
    CUtensorMap*, CUtensorMapDataType, cuuint32_t, void*,
    const cuuint64_t*, const cuuint64_t*, const cuuint32_t*, const cuuint32_t*,
    CUtensorMapInterleave, CUtensorMapSwizzle, CUtensorMapL2promotion,
    CUtensorMapFloatOOBfill);

extern "C" void kernel_launch(void* const* d_in, const int* in_sizes, int n_in,
                              void* d_out, int out_size) {
    const int*   x    = (const int*)d_in[0];
    const int*   w    = (const int*)d_in[1];
    const float* bias = (const float*)d_in[2];
    const float* xsc  = (const float*)d_in[3];
    const float* wsc  = (const float*)d_in[4];
    float* out = (float*)d_out;

    void* xb_ptr = nullptr;
    void* wb_ptr = nullptr;
    cudaGetSymbolAddress(&xb_ptr, g_xb);
    cudaGetSymbolAddress(&wb_ptr, g_wb);

    // Pre-pass: int32 -> (bf16 | int8), matching whichever GEMM variant loads.
    {
        int n4x = TOKENS * IN_F / 4;
        int n4w = OUT_F * IN_F / 4;
        cvt_kernel<<<(n4x + 255) / 256, 256>>>((const int4*)x, xb_ptr, n4x);
        cvt_kernel<<<(n4w + 255) / 256, 256>>>((const int4*)w, wb_ptr, n4w);
    }

    // TMA descriptors: SW128, 128B inner rows, 128-row boxes (A half / B chunk).
    tmencode_fn_t enc = nullptr;
    {
        void* fn = nullptr;
        cudaDriverEntryPointQueryResult qres;
#if CUDART_VERSION >= 12050
        cudaGetDriverEntryPointByVersion("cuTensorMapEncodeTiled", &fn, 12000,
                                         cudaEnableDefault, &qres);
#else
        cudaGetDriverEntryPoint("cuTensorMapEncodeTiled", &fn,
                                cudaEnableDefault, &qres);
#endif
        enc = (tmencode_fn_t)fn;
    }

    alignas(64) CUtensorMap tmA, tmB;
    if (enc) {
        {
            cuuint64_t dims[2] = {IN_F, TOKENS};
            cuuint64_t strd[1] = {IN_F * 2ull};
            cuuint32_t box[2]  = {KC, 128};             // 64 bf16 = 128B inner
            cuuint32_t es[2]   = {1, 1};
            enc(&tmA, CU_TENSOR_MAP_DATA_TYPE_BFLOAT16, 2, xb_ptr, dims, strd, box, es,
                CU_TENSOR_MAP_INTERLEAVE_NONE, CU_TENSOR_MAP_SWIZZLE_128B,
                CU_TENSOR_MAP_L2_PROMOTION_L2_128B, CU_TENSOR_MAP_FLOAT_OOB_FILL_NONE);
        }
        {
            cuuint64_t dims[2] = {IN_F, OUT_F};
            cuuint64_t strd[1] = {IN_F * 2ull};
            cuuint32_t box[2]  = {KC, 128};
            cuuint32_t es[2]   = {1, 1};
            enc(&tmB, CU_TENSOR_MAP_DATA_TYPE_BFLOAT16, 2, wb_ptr, dims, strd, box, es,
                CU_TENSOR_MAP_INTERLEAVE_NONE, CU_TENSOR_MAP_SWIZZLE_128B,
                CU_TENSOR_MAP_L2_PROMOTION_L2_128B, CU_TENSOR_MAP_FLOAT_OOB_FILL_NONE);
        }
    }

    cudaFuncSetAttribute(q8gemm_kernel,
                         cudaFuncAttributeMaxDynamicSharedMemorySize, SMEM_TOTAL);

    // Persistent grid: exactly one CTA per SM (cluster pairs).
    int sms = 148;
    cudaDeviceGetAttribute(&sms, cudaDevAttrMultiProcessorCount, 0);
    const int nslots = sms / 2;
    const int grid   = nslots * 2;
    q8gemm_kernel<<<grid, GTHREADS, SMEM_TOTAL>>>(tmA, tmB, bias, xsc, wsc, out, nslots);
}

// round 15
// speedup vs baseline: 1.0777x; 1.0041x over previous
#include <cuda_runtime.h>
#include <cuda.h>
#include <cuda_bf16.h>
#include <cstdint>

// ---------------------------------------------------------------------------
// Problem constants
// ---------------------------------------------------------------------------
#define TOKENS 8192
#define IN_F   4096
#define OUT_F  16384

#define TILE_MP 256                  // M per cluster pair (128 per CTA)
#define TILE_NP 512                  // N per cluster pair (2 x N=256 MMAs)
#define GTHREADS 256                 // w0=producer, w1=control, w4-7=epilogue
#define CLUSTER 2
#define NT_TOTAL 1024                // 32 m-pairs x 32 n-tiles

// SW64 atoms: 32 bf16 per stage-row (64B rows) — validated R10
#define KC     32
#define NKI    (IN_F / KC)           // 128 K-iterations per tile
#define NSTAGE 8                     // ring over a GLOBAL generation counter

// Per-CTA stage: A 128x64B (8KB) + B 2x128x64B (16KB) = 24KB
#define SM_TMEMPTR 0
#define SM_FULL(s)  (64  + (s) * 8)   // 64..127
#define SM_DONE(s)  (192 + (s) * 8)   // 192..255
#define SM_PRDY(s)  (320 + (s) * 8)   // 320..383
#define SM_FINAL    448
#define SM_EPIFREE  456
#define SM_TILES    1024
#define A_BYTES     (128 * KC * 2)            // 8192
#define B_CHUNK     (128 * KC * 2)            // 8192
#define STAGE_BYTES (A_BYTES + 2 * B_CHUNK)   // 24576
#define SM_A(s) (SM_TILES + (s) * STAGE_BYTES)
#define SM_B(s) (SM_A(s) + A_BYTES)
#define SM_SCALES  (SM_TILES + NSTAGE * STAGE_BYTES)     // 197632
#define SMEM_TOTAL (SM_SCALES + 2 * TILE_NP * 4)          // 201728 (1 CTA/SM)

// Arch-specific feature gate: tcgen05 legal only on sm_100a / sm_103a targets.
#if defined(__CUDA_ARCH_FEAT_SM103_ALL) || defined(__CUDA_ARCH_FEAT_SM100_ALL)
#define HAS_TCGEN05 1
#else
#define HAS_TCGEN05 0
#endif

// idesc, kind::f16 cg2: dtype=F32, a=BF16, b=BF16, N=256, M_TOTAL=256.
// (Validated R11-R14: passed, rel_err 5.7e-8.)
static constexpr uint32_t MMA_IDESC_CG2 =
    (1u << 4) | (1u << 7) | (1u << 10) | ((256u / 8u) << 17) | ((256u / 16u) << 24);

// Scratch (device-global scratch is the sanctioned no-alloc path).
__device__ __nv_bfloat16 g_xb[(size_t)TOKENS * IN_F];   // 64 MB
__device__ __nv_bfloat16 g_wb[(size_t)OUT_F * IN_F];    // 128 MB

// ---------------------------------------------------------------------------
// Common PTX helpers
// ---------------------------------------------------------------------------
__device__ __forceinline__ uint32_t elect_one_pred() {
    uint32_t pred;
    asm volatile(
        "{\n\t.reg .pred p;\n\telect.sync _|p, 0xFFFFFFFF;\n\t"
        "selp.b32 %0, 1, 0, p;\n\t}" : "=r"(pred));
    return pred;
}

__device__ __forceinline__ uint32_t smem_u32(const void* p) {
    uint32_t a;
    asm("{ .reg .u64 t; cvta.to.shared.u64 t, %1; cvt.u32.u64 %0, t; }"
        : "=r"(a) : "l"(p));
    return a;
}

#define MBARRIER_INIT(addr, cnt) \
    asm volatile("mbarrier.init.shared.b64 [%0], %1;" :: "r"((uint32_t)(addr)), "r"((uint32_t)(cnt)) : "memory")

#define MBARRIER_EXPECT_TX(addr, tx) \
    asm volatile("mbarrier.arrive.expect_tx.shared.b64 _, [%0], %1;" :: "r"((uint32_t)(addr)), "r"((uint32_t)(tx)) : "memory")

// Arrive on the mbarrier at the same SMEM offset in cluster CTA `rank`.
#define MBARRIER_ARRIVE_CLUSTER(local_mbar_addr, target_rank) \
    asm volatile( \
        "{\n\t.reg .b32 remAddr32;\n\t" \
        "mapa.shared::cluster.u32 remAddr32, %0, %1;\n\t" \
        "mbarrier.arrive.shared::cluster.b64 _, [remAddr32];\n\t}" \
        :: "r"((uint32_t)(local_mbar_addr)), "r"((uint32_t)(target_rank)) : "memory")

#define MBARRIER_WAIT_PARITY(mbar_smem_addr, phase_parity) do { \
    uint32_t _mbar = (uint32_t)(mbar_smem_addr); \
    uint32_t _parity = (uint32_t)(phase_parity); \
    uint32_t _done_; \
    asm volatile( \
        "{\n\t.reg .pred p;\n\t" \
        "mbarrier.try_wait.parity.acquire.cta.shared::cta.b64 p, [%1], %2;\n\t" \
        "selp.b32 %0, 1, 0, p;\n\t}" \
        : "=r"(_done_) : "r"(_mbar), "r"(_parity) : "memory"); \
    if (!_done_) { \
        asm volatile( \
            "{\n\t.reg .pred P1;\n\t" \
            "WAIT_LOOP_%=:\n\t" \
            "mbarrier.try_wait.parity.acquire.cta.shared::cta.b64 P1, [%0], %1, 0x989680;\n\t" \
            "@P1 bra.uni WAIT_DONE_%=;\n\t" \
            "bra.uni WAIT_LOOP_%=;\n\t" \
            "WAIT_DONE_%=:\n\t}" \
            :: "r"(_mbar), "r"(_parity) : "memory"); \
    } \
} while (0)

#define CLUSTER_SYNC() do { \
    asm volatile("barrier.cluster.arrive.aligned;" ::: "memory"); \
    asm volatile("barrier.cluster.wait.aligned;"   ::: "memory"); \
} while (0)

#define NAMED_BAR_EPI() asm volatile("bar.sync 1, 128;" ::: "memory")

// ---------------------------------------------------------------------------
// tcgen05 cg2 macros
// ---------------------------------------------------------------------------
#define TCGEN05_ALLOC_CG2(smem_result_addr, nCols) \
    asm volatile("tcgen05.alloc.cta_group::2.sync.aligned.shared::cta.b32 [%0], %1;" \
        :: "r"((uint32_t)(smem_result_addr)), "r"((uint32_t)(nCols)) : "memory")

#define TCGEN05_DEALLOC_CG2(tmem_addr, nCols) \
    asm volatile("tcgen05.dealloc.cta_group::2.sync.aligned.b32 %0, %1;" \
        :: "r"(tmem_addr), "r"((uint32_t)(nCols)))

#define TCGEN05_RELINQUISH_CG2() \
    asm volatile("tcgen05.relinquish_alloc_permit.cta_group::2.sync.aligned;")

#define TCGEN05_COMMIT_MC_CG2(mbar_smem_addr, mask) \
    asm volatile("tcgen05.commit.cta_group::2.mbarrier::arrive::one.shared::cluster.multicast::cluster.b64 [%0], %1;" \
        :: "r"((uint32_t)(mbar_smem_addr)), "h"((uint16_t)(mask)) : "memory")

#define TCGEN05_WAIT_LD() \
    asm volatile("tcgen05.wait::ld.sync.aligned;" ::: "memory")

#define TCGEN05_FENCE_BEFORE() \
    asm volatile("tcgen05.fence::before_thread_sync;" ::: "memory")

#define TCGEN05_FENCE_AFTER() \
    asm volatile("tcgen05.fence::after_thread_sync;" ::: "memory")

#define TCGEN05_LD_32X32B_X32(r, tmem_addr) \
    asm volatile( \
        "tcgen05.ld.sync.aligned.32x32b.x32.b32 " \
        "{%0, %1, %2, %3, %4, %5, %6, %7, " \
        " %8, %9, %10, %11, %12, %13, %14, %15, " \
        " %16, %17, %18, %19, %20, %21, %22, %23, " \
        " %24, %25, %26, %27, %28, %29, %30, %31}, [%32];" \
        : "=r"((r)[0]),  "=r"((r)[1]),  "=r"((r)[2]),  "=r"((r)[3]), \
          "=r"((r)[4]),  "=r"((r)[5]),  "=r"((r)[6]),  "=r"((r)[7]), \
          "=r"((r)[8]),  "=r"((r)[9]),  "=r"((r)[10]), "=r"((r)[11]), \
          "=r"((r)[12]), "=r"((r)[13]), "=r"((r)[14]), "=r"((r)[15]), \
          "=r"((r)[16]), "=r"((r)[17]), "=r"((r)[18]), "=r"((r)[19]), \
          "=r"((r)[20]), "=r"((r)[21]), "=r"((r)[22]), "=r"((r)[23]), \
          "=r"((r)[24]), "=r"((r)[25]), "=r"((r)[26]), "=r"((r)[27]), \
          "=r"((r)[28]), "=r"((r)[29]), "=r"((r)[30]), "=r"((r)[31]) \
        : "r"(tmem_addr))

// SW64 K-major descriptor: layout=4, version=1, SBO=32 (512B atom), LBO=1.
// (Validated R10: passed with SW64 TMA + these fields.)
static constexpr unsigned long long SMEM_DESC_BASE_SW64 =
    (4ull << 61) | (1ull << 46) | (32ull << 32) | (1ull << 16);

__device__ __forceinline__ uint64_t make_desc64(uint32_t smem_addr) {
    return SMEM_DESC_BASE_SW64 | ((uint64_t)(smem_addr >> 4) & 0x3FFFull);
}

// Band-local tile mapping (8-n-tile bands keep a 32MB B band L2-resident).
__device__ __forceinline__ void tile_coords(int t, int rank, int& m0c, int& n0) {
    const int band = t >> 8;           // 256 tiles per band
    const int r    = t & 255;
    const int mtp  = r >> 3;
    const int nt   = (band << 3) + (r & 7);
    m0c = mtp * TILE_MP + rank * 128;
    n0  = nt * TILE_NP;
}

#if HAS_TCGEN05
// cg2 bf16 SS MMA (8 zero regs for disable-output-lane).
__device__ __forceinline__ void mma_bf16_ss_cg2(uint32_t d_tmem, uint64_t a_desc,
                                                uint64_t b_desc, uint32_t idesc,
                                                uint32_t enable_d) {
    asm volatile(
        "{\n\t.reg .pred p;\n\t"
        "setp.ne.u32 p, %5, 0;\n\t"
        "tcgen05.mma.cta_group::2.kind::f16 [%0], %1, %2, %3, "
        "{%4, %4, %4, %4, %4, %4, %4, %4}, p;\n\t}"
        :: "r"(d_tmem), "l"(a_desc), "l"(b_desc), "r"(idesc), "r"(0u), "r"(enable_d)
        : "memory");
}

__device__ __forceinline__ void tma_ld2(uint32_t smem_addr, const CUtensorMap* tmap,
                                        int cx, int cy, uint32_t mbar) {
    asm volatile(
        "cp.async.bulk.tensor.2d.shared::cta.global.tile.mbarrier::complete_tx::bytes "
        "[%0], [%1, {%2, %3}], [%4];"
        :: "r"(smem_addr), "l"(tmap), "r"(cx), "r"(cy), "r"(mbar) : "memory");
}
#endif

// ---------------------------------------------------------------------------
// Fallback helpers: ldmatrix + int8 mma.sync (family-portable)
// ---------------------------------------------------------------------------
__device__ __forceinline__ void ldsm_x4(uint32_t& r0, uint32_t& r1,
                                        uint32_t& r2, uint32_t& r3, uint32_t addr) {
    asm volatile("ldmatrix.sync.aligned.m8n8.x4.shared.b16 {%0,%1,%2,%3}, [%4];"
                 : "=r"(r0), "=r"(r1), "=r"(r2), "=r"(r3) : "r"(addr));
}

__device__ __forceinline__ void imma16832(int* c, const uint32_t* a, const uint32_t* b) {
    asm volatile(
        "mma.sync.aligned.m16n8k32.row.col.s32.s8.s8.s32 "
        "{%0,%1,%2,%3}, {%4,%5,%6,%7}, {%8,%9}, {%0,%1,%2,%3};"
        : "+r"(c[0]), "+r"(c[1]), "+r"(c[2]), "+r"(c[3])
        : "r"(a[0]), "r"(a[1]), "r"(a[2]), "r"(a[3]), "r"(b[0]), "r"(b[1]));
}

// ---------------------------------------------------------------------------
// Pre-pass: int32 -> bf16 (tcgen05 path) or int8 (fallback path)
// ---------------------------------------------------------------------------
__global__ void cvt_kernel(const int4* __restrict__ in, void* __restrict__ out, int n4) {
    int i = blockIdx.x * blockDim.x + threadIdx.x;
    if (i >= n4) return;
    int4 v = in[i];
#if HAS_TCGEN05
    __nv_bfloat162 p0, p1;
    p0.x = __int2bfloat16_rn(v.x); p0.y = __int2bfloat16_rn(v.y);
    p1.x = __int2bfloat16_rn(v.z); p1.y = __int2bfloat16_rn(v.w);
    uint2 o;
    o.x = *reinterpret_cast<unsigned*>(&p0);
    o.y = *reinterpret_cast<unsigned*>(&p1);
    reinterpret_cast<uint2*>(out)[i] = o;
#else
    char4 o;
    o.x = (char)v.x; o.y = (char)v.y; o.z = (char)v.z; o.w = (char)v.w;
    reinterpret_cast<char4*>(out)[i] = o;
#endif
}

// ---------------------------------------------------------------------------
// PERSISTENT GEMM, 8-stage SW64 ring: the deeper ring (~4.6us of buffered
// TMA) lets the producer stream straight through each tile's epilogue, so
// the EPI_FREE stall is repaid from buffered stages at tensor rate.
// ---------------------------------------------------------------------------
__global__ void __launch_bounds__(GTHREADS) __cluster_dims__(CLUSTER, 1, 1)
q8gemm_kernel(
    const __grid_constant__ CUtensorMap tmA,
    const __grid_constant__ CUtensorMap tmB,
    const float* __restrict__ bias,
    const float* __restrict__ xsc,
    const float* __restrict__ wsc,
    float* __restrict__ out,
    int nslots)
{
    extern __shared__ __align__(1024) char smem[];
    const int tid  = threadIdx.x;
    const int wid  = tid >> 5;
    const int lid  = tid & 31;
    const int rank = blockIdx.x & 1;             // cluster rank
    const int slot = blockIdx.x >> 1;            // persistent pair slot

#if HAS_TCGEN05
    const uint32_t sb = smem_u32(smem);

    if (wid == 0) TCGEN05_ALLOC_CG2(sb + SM_TMEMPTR, 512);
    if (tid == 0) {
        #pragma unroll
        for (int s = 0; s < NSTAGE; s++) {
            MBARRIER_INIT(sb + SM_FULL(s), 1);
            MBARRIER_INIT(sb + SM_DONE(s), 1);
            MBARRIER_INIT(sb + SM_PRDY(s), 1);
        }
        MBARRIER_INIT(sb + SM_FINAL, 1);
        MBARRIER_INIT(sb + SM_EPIFREE, 2);   // one arrive per CTA's epilogue
    }
    __syncthreads();
    CLUSTER_SYNC();

    uint32_t tbase;
    asm volatile("ld.shared.b32 %0, [%1];" : "=r"(tbase) : "r"(sb + SM_TMEMPTR));

    if (wid == 0) {
        // ================= producer: one continuous TMA stream =================
        if (elect_one_pred()) {
            int g = 0;
            for (int t = slot; t < NT_TOTAL; t += nslots) {
                int m0c, n0; tile_coords(t, rank, m0c, n0);
                for (int ks = 0; ks < NKI; ks++, g++) {
                    const int s = g & (NSTAGE - 1);
                    if (g >= NSTAGE)
                        MBARRIER_WAIT_PARITY(sb + SM_DONE(s), ((g - NSTAGE) >> 3) & 1);
                    MBARRIER_EXPECT_TX(sb + SM_FULL(s), STAGE_BYTES);
                    tma_ld2(sb + SM_A(s),           &tmA, ks * KC, m0c,                   sb + SM_FULL(s));
                    tma_ld2(sb + SM_B(s),           &tmB, ks * KC, n0 + rank * 128,       sb + SM_FULL(s));
                    tma_ld2(sb + SM_B(s) + B_CHUNK, &tmB, ks * KC, n0 + 256 + rank * 128, sb + SM_FULL(s));
                }
            }
        }
    } else if (wid == 1) {
        // ============== control: MMA driver (leader) / forwarder (peer) =========
        if (rank == 0) {
            if (elect_one_pred()) {
                int g = 0, ti = 0;
                for (int t = slot; t < NT_TOTAL; t += nslots, ti++) {
                    if (ti >= 1) {                       // TMEM free after prev epilogue
                        MBARRIER_WAIT_PARITY(sb + SM_EPIFREE, (ti - 1) & 1);
                        TCGEN05_FENCE_AFTER();
                    }
                    for (int ks = 0; ks < NKI; ks++, g++) {
                        const int s  = g & (NSTAGE - 1);
                        const int ph = (g >> 3) & 1;
                        MBARRIER_WAIT_PARITY(sb + SM_FULL(s), ph);
                        MBARRIER_WAIT_PARITY(sb + SM_PRDY(s), ph);
                        uint64_t ad = make_desc64(sb + SM_A(s));
                        uint64_t b0 = make_desc64(sb + SM_B(s));
                        uint64_t b1 = make_desc64(sb + SM_B(s) + B_CHUNK);
                        #pragma unroll
                        for (int j = 0; j < 2; j++) {    // 2 x K16 = K32
                            uint32_t e = (uint32_t)((ks | j) != 0);
                            mma_bf16_ss_cg2(tbase,       ad + j * 2, b0 + j * 2, MMA_IDESC_CG2, e);
                            mma_bf16_ss_cg2(tbase + 256, ad + j * 2, b1 + j * 2, MMA_IDESC_CG2, e);
                        }
                        TCGEN05_COMMIT_MC_CG2(sb + SM_DONE(s), 0x3);
                    }
                    TCGEN05_COMMIT_MC_CG2(sb + SM_FINAL, 0x3);
                }
            }
        } else {
            if (elect_one_pred()) {
                int g = 0;
                for (int t = slot; t < NT_TOTAL; t += nslots)
                    for (int ks = 0; ks < NKI; ks++, g++) {
                        const int s  = g & (NSTAGE - 1);
                        const int ph = (g >> 3) & 1;
                        MBARRIER_WAIT_PARITY(sb + SM_FULL(s), ph);
                        MBARRIER_ARRIVE_CLUSTER(sb + SM_PRDY(s), 0);
                    }
            }
        }
    } else if (wid >= 4) {
        // ======================== epilogue: warps 4-7 ==========================
        float* s_ws = reinterpret_cast<float*>(smem + SM_SCALES);
        float* s_bi = s_ws + TILE_NP;
        const int etid = tid - 128;          // 0..127
        int ti = 0;
        for (int t = slot; t < NT_TOTAL; t += nslots, ti++) {
            int m0c, n0; tile_coords(t, rank, m0c, n0);
            for (int i = etid; i < TILE_NP; i += 128) {
                s_ws[i] = wsc[n0 + i];
                s_bi[i] = bias[n0 + i];
            }
            NAMED_BAR_EPI();
            MBARRIER_WAIT_PARITY(sb + SM_FINAL, ti & 1);
            TCGEN05_FENCE_AFTER();

            const int row = m0c + (wid & 3) * 32 + lid;
            const float xsv = xsc[row];
            float* orow = out + (size_t)row * OUT_F + n0;
            #pragma unroll 1
            for (int cb = 0; cb < TILE_NP / 32; cb += 2) {   // 2 blocks per wait
                uint32_t rg[2][32];
                TCGEN05_LD_32X32B_X32(rg[0], tbase + cb * 32);
                TCGEN05_LD_32X32B_X32(rg[1], tbase + (cb + 1) * 32);
                TCGEN05_WAIT_LD();
                #pragma unroll
                for (int h = 0; h < 2; h++) {
                    #pragma unroll
                    for (int q = 0; q < 8; q++) {
                        const int c = (cb + h) * 32 + q * 4;
                        float4 v;
                        v.x = fmaf(__uint_as_float(rg[h][q * 4 + 0]), xsv * s_ws[c + 0], s_bi[c + 0]);
                        v.y = fmaf(__uint_as_float(rg[h][q * 4 + 1]), xsv * s_ws[c + 1], s_bi[c + 1]);
                        v.z = fmaf(__uint_as_float(rg[h][q * 4 + 2]), xsv * s_ws[c + 2], s_bi[c + 2]);
                        v.w = fmaf(__uint_as_float(rg[h][q * 4 + 3]), xsv * s_ws[c + 3], s_bi[c + 3]);
                        *reinterpret_cast<float4*>(orow + c) = v;
                    }
                }
            }
            TCGEN05_FENCE_BEFORE();
            NAMED_BAR_EPI();                 // all epilogue reads (TMEM + s_ws) done
            if (wid == 4 && elect_one_pred())
                MBARRIER_ARRIVE_CLUSTER(sb + SM_EPIFREE, 0);   // to leader
        }
    }

    __syncthreads();
    if (wid == 0) {
        TCGEN05_RELINQUISH_CG2();
        TCGEN05_DEALLOC_CG2(tbase, 512);
    }
    CLUSTER_SYNC();

#else
    // =================== portable int8 mma.sync fallback ===================
    const int8_t* x8 = reinterpret_cast<const int8_t*>(g_xb);
    const int8_t* w8 = reinterpret_cast<const int8_t*>(g_wb);

    const int AST = 80, BST = 80;
    char* sA = smem;
    char* sB = smem + 128 * AST;
    const uint32_t sAu = smem_u32(sA);
    const uint32_t sBu = smem_u32(sB);
    const int warp_row = (wid & 3) * 32;

    for (int t = slot; t < NT_TOTAL; t += nslots) {
        int m0c, n0; tile_coords(t, rank, m0c, n0);
        for (int nc = 0; nc < 8; nc++) {
            const int nb = n0 + nc * 64;
            int acc[2][8][4];
            #pragma unroll
            for (int a = 0; a < 2; a++)
                #pragma unroll
                for (int b = 0; b < 8; b++)
                    #pragma unroll
                    for (int c = 0; c < 4; c++) acc[a][b][c] = 0;

            for (int kt = 0; kt < 64; kt++) {
                const int k0 = kt * 64;
                __syncthreads();
                if (tid < 128) {
                    const uint4* src = reinterpret_cast<const uint4*>(
                        x8 + (size_t)(m0c + tid) * IN_F + k0);
                    uint4* dst = reinterpret_cast<uint4*>(sA + tid * AST);
                    #pragma unroll
                    for (int j = 0; j < 4; j++) dst[j] = src[j];
                    const int br = tid >> 1, hh = tid & 1;
                    const uint4* src2 = reinterpret_cast<const uint4*>(
                        w8 + (size_t)(nb + br) * IN_F + k0 + hh * 32);
                    uint4* dst2 = reinterpret_cast<uint4*>(sB + br * BST + hh * 32);
                    dst2[0] = src2[0]; dst2[1] = src2[1];
                }
                __syncthreads();

                if (tid < 128) {
                    #pragma unroll
                    for (int s = 0; s < 2; s++) {
                        uint32_t afr[2][4];
                        #pragma unroll
                        for (int mt2 = 0; mt2 < 2; mt2++) {
                            uint32_t addr = sAu +
                                (uint32_t)(warp_row + mt2 * 16 + (lid & 15)) * AST +
                                s * 32 + ((lid >= 16) ? 16 : 0);
                            ldsm_x4(afr[mt2][0], afr[mt2][1], afr[mt2][2], afr[mt2][3], addr);
                        }
                        uint32_t bfr[4][4];
                        #pragma unroll
                        for (int p = 0; p < 4; p++) {
                            uint32_t addr = sBu +
                                (uint32_t)(p * 16 + (lid & 7) + ((lid >= 16) ? 8 : 0)) * BST +
                                s * 32 + ((lid & 8) ? 16 : 0);
                            ldsm_x4(bfr[p][0], bfr[p][1], bfr[p][2], bfr[p][3], addr);
                        }
                        #pragma unroll
                        for (int mt2 = 0; mt2 < 2; mt2++)
                            #pragma unroll
                            for (int nt2 = 0; nt2 < 8; nt2++) {
                                uint32_t bb[2];
                                bb[0] = bfr[nt2 >> 1][(nt2 & 1) ? 2 : 0];
                                bb[1] = bfr[nt2 >> 1][(nt2 & 1) ? 3 : 1];
                                imma16832(acc[mt2][nt2], afr[mt2], bb);
                            }
                    }
                }
            }
            if (tid < 128) {
                #pragma unroll
                for (int mt2 = 0; mt2 < 2; mt2++) {
                    const int r0_ = m0c + warp_row + mt2 * 16 + (lid >> 2);
                    const float xs0 = xsc[r0_], xs1 = xsc[r0_ + 8];
                    #pragma unroll
                    for (int nt2 = 0; nt2 < 8; nt2++) {
                        const int c0 = nb + nt2 * 8 + (lid & 3) * 2;
                        const float w0 = wsc[c0], w1 = wsc[c0 + 1];
                        const float b0 = bias[c0], b1 = bias[c0 + 1];
                        float* o0 = out + (size_t)r0_ * OUT_F + c0;
                        float* o1 = out + (size_t)(r0_ + 8) * OUT_F + c0;
                        o0[0] = fmaf((float)acc[mt2][nt2][0], xs0 * w0, b0);
                        o0[1] = fmaf((float)acc[mt2][nt2][1], xs0 * w1, b1);
                        o1[0] = fmaf((float)acc[mt2][nt2][2], xs1 * w0, b0);
                        o1[1] = fmaf((float)acc[mt2][nt2][3], xs1 * w1, b1);
                    }
                }
            }
        }
    }
#endif
}

// ---------------------------------------------------------------------------
// Host launcher
// ---------------------------------------------------------------------------
typedef CUresult (*tmencode_fn_t)(
    CUtensorMap*, CUtensorMapDataType, cuuint32_t, void*,
    const cuuint64_t*, const cuuint64_t*, const cuuint32_t*, const cuuint32_t*,
    CUtensorMapInterleave, CUtensorMapSwizzle, CUtensorMapL2promotion,
    CUtensorMapFloatOOBfill);

extern "C" void kernel_launch(void* const* d_in, const int* in_sizes, int n_in,
                              void* d_out, int out_size) {
    const int*   x    = (const int*)d_in[0];
    const int*   w    = (const int*)d_in[1];
    const float* bias = (const float*)d_in[2];
    const float* xsc  = (const float*)d_in[3];
    const float* wsc  = (const float*)d_in[4];
    float* out = (float*)d_out;

    void* xb_ptr = nullptr;
    void* wb_ptr = nullptr;
    cudaGetSymbolAddress(&xb_ptr, g_xb);
    cudaGetSymbolAddress(&wb_ptr, g_wb);

    // Pre-pass: int32 -> (bf16 | int8), matching whichever GEMM variant loads.
    {
        int n4x = TOKENS * IN_F / 4;
        int n4w = OUT_F * IN_F / 4;
        cvt_kernel<<<(n4x + 255) / 256, 256>>>((const int4*)x, xb_ptr, n4x);
        cvt_kernel<<<(n4w + 255) / 256, 256>>>((const int4*)w, wb_ptr, n4w);
    }

    // TMA descriptors: SW64, 64B inner rows, 128-row boxes (A half / B chunk).
    tmencode_fn_t enc = nullptr;
    {
        void* fn = nullptr;
        cudaDriverEntryPointQueryResult qres;
#if CUDART_VERSION >= 12050
        cudaGetDriverEntryPointByVersion("cuTensorMapEncodeTiled", &fn, 12000,
                                         cudaEnableDefault, &qres);
#else
        cudaGetDriverEntryPoint("cuTensorMapEncodeTiled", &fn,
                                cudaEnableDefault, &qres);
#endif
        enc = (tmencode_fn_t)fn;
    }

    alignas(64) CUtensorMap tmA, tmB;
    if (enc) {
        {
            cuuint64_t dims[2] = {IN_F, TOKENS};
            cuuint64_t strd[1] = {IN_F * 2ull};
            cuuint32_t box[2]  = {KC, 128};             // 32 bf16 = 64B inner
            cuuint32_t es[2]   = {1, 1};
            enc(&tmA, CU_TENSOR_MAP_DATA_TYPE_BFLOAT16, 2, xb_ptr, dims, strd, box, es,
                CU_TENSOR_MAP_INTERLEAVE_NONE, CU_TENSOR_MAP_SWIZZLE_64B,
                CU_TENSOR_MAP_L2_PROMOTION_L2_128B, CU_TENSOR_MAP_FLOAT_OOB_FILL_NONE);
        }
        {
            cuuint64_t dims[2] = {IN_F, OUT_F};
            cuuint64_t strd[1] = {IN_F * 2ull};
            cuuint32_t box[2]  = {KC, 128};
            cuuint32_t es[2]   = {1, 1};
            enc(&tmB, CU_TENSOR_MAP_DATA_TYPE_BFLOAT16, 2, wb_ptr, dims, strd, box, es,
                CU_TENSOR_MAP_INTERLEAVE_NONE, CU_TENSOR_MAP_SWIZZLE_64B,
                CU_TENSOR_MAP_L2_PROMOTION_L2_128B, CU_TENSOR_MAP_FLOAT_OOB_FILL_NONE);
        }
    }

    cudaFuncSetAttribute(q8gemm_kernel,
                         cudaFuncAttributeMaxDynamicSharedMemorySize, SMEM_TOTAL);

    // Persistent grid: exactly one CTA per SM (cluster pairs).
    int sms = 148;
    cudaDeviceGetAttribute(&sms, cudaDevAttrMultiProcessorCount, 0);
    const int nslots = sms / 2;
    const int grid   = nslots * 2;
    q8gemm_kernel<<<grid, GTHREADS, SMEM_TOTAL>>>(tmA, tmB, bias, xsc, wsc, out, nslots);
}

// round 16
// speedup vs baseline: 1.0791x; 1.0013x over previous
#include <cuda_runtime.h>
#include <cuda.h>
#include <cuda_bf16.h>
#include <cstdint>

// ---------------------------------------------------------------------------
// Problem constants
// ---------------------------------------------------------------------------
#define TOKENS 8192
#define IN_F   4096
#define OUT_F  16384

#define TILE_MP 256                  // M per cluster pair (128 per CTA)
#define TILE_NP 512                  // N per cluster pair (2 x N=256 MMAs)
#define GTHREADS 256                 // w0=producer, w1=control, w4-7=epilogue
#define CLUSTER 2
#define NT_TOTAL 1024                // 32 m-pairs x 32 n-tiles

// SW64 atoms: 32 bf16 per stage-row (64B rows) — validated R10/R15
#define KC     32
#define NKI    (IN_F / KC)           // 128 K-iterations per tile
#define NSTAGE 8                     // ring over a GLOBAL generation counter

// Per-CTA stage: A 128x64B (8KB) + B 2x128x64B (16KB) = 24KB
#define SM_TMEMPTR 0
#define SM_FULL(s)  (64  + (s) * 8)   // 64..127
#define SM_DONE(s)  (192 + (s) * 8)   // 192..255
#define SM_PRDY(s)  (320 + (s) * 8)   // 320..383
#define SM_FINAL    448
#define SM_EPIFREE0 456
#define SM_EPIFREE1 464
#define SM_TILES    1024
#define A_BYTES     (128 * KC * 2)            // 8192
#define B_CHUNK     (128 * KC * 2)            // 8192
#define STAGE_BYTES (A_BYTES + 2 * B_CHUNK)   // 24576
#define SM_A(s) (SM_TILES + (s) * STAGE_BYTES)
#define SM_B(s) (SM_A(s) + A_BYTES)
#define SM_SCALES  (SM_TILES + NSTAGE * STAGE_BYTES)     // 197632
#define SMEM_TOTAL (SM_SCALES + 2 * TILE_NP * 4)          // 201728 (1 CTA/SM)

// Arch-specific feature gate: tcgen05 legal only on sm_100a / sm_103a targets.
#if defined(__CUDA_ARCH_FEAT_SM103_ALL) || defined(__CUDA_ARCH_FEAT_SM100_ALL)
#define HAS_TCGEN05 1
#else
#define HAS_TCGEN05 0
#endif

// idesc, kind::f16 cg2: dtype=F32, a=BF16, b=BF16, N=256, M_TOTAL=256.
// (Validated R11-R15: passed, rel_err 5.7e-8.)
static constexpr uint32_t MMA_IDESC_CG2 =
    (1u << 4) | (1u << 7) | (1u << 10) | ((256u / 8u) << 17) | ((256u / 16u) << 24);

// Scratch (device-global scratch is the sanctioned no-alloc path).
__device__ __nv_bfloat16 g_xb[(size_t)TOKENS * IN_F];   // 64 MB
__device__ __nv_bfloat16 g_wb[(size_t)OUT_F * IN_F];    // 128 MB

// ---------------------------------------------------------------------------
// Common PTX helpers
// ---------------------------------------------------------------------------
__device__ __forceinline__ uint32_t elect_one_pred() {
    uint32_t pred;
    asm volatile(
        "{\n\t.reg .pred p;\n\telect.sync _|p, 0xFFFFFFFF;\n\t"
        "selp.b32 %0, 1, 0, p;\n\t}" : "=r"(pred));
    return pred;
}

__device__ __forceinline__ uint32_t smem_u32(const void* p) {
    uint32_t a;
    asm("{ .reg .u64 t; cvta.to.shared.u64 t, %1; cvt.u32.u64 %0, t; }"
        : "=r"(a) : "l"(p));
    return a;
}

#define MBARRIER_INIT(addr, cnt) \
    asm volatile("mbarrier.init.shared.b64 [%0], %1;" :: "r"((uint32_t)(addr)), "r"((uint32_t)(cnt)) : "memory")

#define MBARRIER_EXPECT_TX(addr, tx) \
    asm volatile("mbarrier.arrive.expect_tx.shared.b64 _, [%0], %1;" :: "r"((uint32_t)(addr)), "r"((uint32_t)(tx)) : "memory")

// Arrive on the mbarrier at the same SMEM offset in cluster CTA `rank`.
#define MBARRIER_ARRIVE_CLUSTER(local_mbar_addr, target_rank) \
    asm volatile( \
        "{\n\t.reg .b32 remAddr32;\n\t" \
        "mapa.shared::cluster.u32 remAddr32, %0, %1;\n\t" \
        "mbarrier.arrive.shared::cluster.b64 _, [remAddr32];\n\t}" \
        :: "r"((uint32_t)(local_mbar_addr)), "r"((uint32_t)(target_rank)) : "memory")

#define MBARRIER_WAIT_PARITY(mbar_smem_addr, phase_parity) do { \
    uint32_t _mbar = (uint32_t)(mbar_smem_addr); \
    uint32_t _parity = (uint32_t)(phase_parity); \
    uint32_t _done_; \
    asm volatile( \
        "{\n\t.reg .pred p;\n\t" \
        "mbarrier.try_wait.parity.acquire.cta.shared::cta.b64 p, [%1], %2;\n\t" \
        "selp.b32 %0, 1, 0, p;\n\t}" \
        : "=r"(_done_) : "r"(_mbar), "r"(_parity) : "memory"); \
    if (!_done_) { \
        asm volatile( \
            "{\n\t.reg .pred P1;\n\t" \
            "WAIT_LOOP_%=:\n\t" \
            "mbarrier.try_wait.parity.acquire.cta.shared::cta.b64 P1, [%0], %1, 0x989680;\n\t" \
            "@P1 bra.uni WAIT_DONE_%=;\n\t" \
            "bra.uni WAIT_LOOP_%=;\n\t" \
            "WAIT_DONE_%=:\n\t}" \
            :: "r"(_mbar), "r"(_parity) : "memory"); \
    } \
} while (0)

#define CLUSTER_SYNC() do { \
    asm volatile("barrier.cluster.arrive.aligned;" ::: "memory"); \
    asm volatile("barrier.cluster.wait.aligned;"   ::: "memory"); \
} while (0)

#define NAMED_BAR_EPI() asm volatile("bar.sync 1, 128;" ::: "memory")

// ---------------------------------------------------------------------------
// tcgen05 cg2 macros
// ---------------------------------------------------------------------------
#define TCGEN05_ALLOC_CG2(smem_result_addr, nCols) \
    asm volatile("tcgen05.alloc.cta_group::2.sync.aligned.shared::cta.b32 [%0], %1;" \
        :: "r"((uint32_t)(smem_result_addr)), "r"((uint32_t)(nCols)) : "memory")

#define TCGEN05_DEALLOC_CG2(tmem_addr, nCols) \
    asm volatile("tcgen05.dealloc.cta_group::2.sync.aligned.b32 %0, %1;" \
        :: "r"(tmem_addr), "r"((uint32_t)(nCols)))

#define TCGEN05_RELINQUISH_CG2() \
    asm volatile("tcgen05.relinquish_alloc_permit.cta_group::2.sync.aligned;")

#define TCGEN05_COMMIT_MC_CG2(mbar_smem_addr, mask) \
    asm volatile("tcgen05.commit.cta_group::2.mbarrier::arrive::one.shared::cluster.multicast::cluster.b64 [%0], %1;" \
        :: "r"((uint32_t)(mbar_smem_addr)), "h"((uint16_t)(mask)) : "memory")

#define TCGEN05_WAIT_LD() \
    asm volatile("tcgen05.wait::ld.sync.aligned;" ::: "memory")

#define TCGEN05_FENCE_BEFORE() \
    asm volatile("tcgen05.fence::before_thread_sync;" ::: "memory")

#define TCGEN05_FENCE_AFTER() \
    asm volatile("tcgen05.fence::after_thread_sync;" ::: "memory")

#define TCGEN05_LD_32X32B_X32(r, tmem_addr) \
    asm volatile( \
        "tcgen05.ld.sync.aligned.32x32b.x32.b32 " \
        "{%0, %1, %2, %3, %4, %5, %6, %7, " \
        " %8, %9, %10, %11, %12, %13, %14, %15, " \
        " %16, %17, %18, %19, %20, %21, %22, %23, " \
        " %24, %25, %26, %27, %28, %29, %30, %31}, [%32];" \
        : "=r"((r)[0]),  "=r"((r)[1]),  "=r"((r)[2]),  "=r"((r)[3]), \
          "=r"((r)[4]),  "=r"((r)[5]),  "=r"((r)[6]),  "=r"((r)[7]), \
          "=r"((r)[8]),  "=r"((r)[9]),  "=r"((r)[10]), "=r"((r)[11]), \
          "=r"((r)[12]), "=r"((r)[13]), "=r"((r)[14]), "=r"((r)[15]), \
          "=r"((r)[16]), "=r"((r)[17]), "=r"((r)[18]), "=r"((r)[19]), \
          "=r"((r)[20]), "=r"((r)[21]), "=r"((r)[22]), "=r"((r)[23]), \
          "=r"((r)[24]), "=r"((r)[25]), "=r"((r)[26]), "=r"((r)[27]), \
          "=r"((r)[28]), "=r"((r)[29]), "=r"((r)[30]), "=r"((r)[31]) \
        : "r"(tmem_addr))

// SW64 K-major descriptor: layout=4, version=1, SBO=32 (512B atom), LBO=1.
static constexpr unsigned long long SMEM_DESC_BASE_SW64 =
    (4ull << 61) | (1ull << 46) | (32ull << 32) | (1ull << 16);

__device__ __forceinline__ uint64_t make_desc64(uint32_t smem_addr) {
    return SMEM_DESC_BASE_SW64 | ((uint64_t)(smem_addr >> 4) & 0x3FFFull);
}

// Band-local tile mapping (8-n-tile bands keep a 32MB B band L2-resident).
__device__ __forceinline__ void tile_coords(int t, int rank, int& m0c, int& n0) {
    const int band = t >> 8;           // 256 tiles per band
    const int r    = t & 255;
    const int mtp  = r >> 3;
    const int nt   = (band << 3) + (r & 7);
    m0c = mtp * TILE_MP + rank * 128;
    n0  = nt * TILE_NP;
}

#if HAS_TCGEN05
// cg2 bf16 SS MMA (8 zero regs for disable-output-lane).
__device__ __forceinline__ void mma_bf16_ss_cg2(uint32_t d_tmem, uint64_t a_desc,
                                                uint64_t b_desc, uint32_t idesc,
                                                uint32_t enable_d) {
    asm volatile(
        "{\n\t.reg .pred p;\n\t"
        "setp.ne.u32 p, %5, 0;\n\t"
        "tcgen05.mma.cta_group::2.kind::f16 [%0], %1, %2, %3, "
        "{%4, %4, %4, %4, %4, %4, %4, %4}, p;\n\t}"
        :: "r"(d_tmem), "l"(a_desc), "l"(b_desc), "r"(idesc), "r"(0u), "r"(enable_d)
        : "memory");
}

__device__ __forceinline__ void tma_ld2(uint32_t smem_addr, const CUtensorMap* tmap,
                                        int cx, int cy, uint32_t mbar) {
    asm volatile(
        "cp.async.bulk.tensor.2d.shared::cta.global.tile.mbarrier::complete_tx::bytes "
        "[%0], [%1, {%2, %3}], [%4];"
        :: "r"(smem_addr), "l"(tmap), "r"(cx), "r"(cy), "r"(mbar) : "memory");
}
#endif

// ---------------------------------------------------------------------------
// Fallback helpers: ldmatrix + int8 mma.sync (family-portable)
// ---------------------------------------------------------------------------
__device__ __forceinline__ void ldsm_x4(uint32_t& r0, uint32_t& r1,
                                        uint32_t& r2, uint32_t& r3, uint32_t addr) {
    asm volatile("ldmatrix.sync.aligned.m8n8.x4.shared.b16 {%0,%1,%2,%3}, [%4];"
                 : "=r"(r0), "=r"(r1), "=r"(r2), "=r"(r3) : "r"(addr));
}

__device__ __forceinline__ void imma16832(int* c, const uint32_t* a, const uint32_t* b) {
    asm volatile(
        "mma.sync.aligned.m16n8k32.row.col.s32.s8.s8.s32 "
        "{%0,%1,%2,%3}, {%4,%5,%6,%7}, {%8,%9}, {%0,%1,%2,%3};"
        : "+r"(c[0]), "+r"(c[1]), "+r"(c[2]), "+r"(c[3])
        : "r"(a[0]), "r"(a[1]), "r"(a[2]), "r"(a[3]), "r"(b[0]), "r"(b[1]));
}

// ---------------------------------------------------------------------------
// FUSED pre-pass: one launch converts BOTH tensors (x then w).
// (Also shifts launch parity so ncu -s 5 captures the GEMM, not cvt.)
// ---------------------------------------------------------------------------
__global__ void cvt_fused_kernel(const int4* __restrict__ xin, const int4* __restrict__ win,
                                 void* __restrict__ xout, void* __restrict__ wout,
                                 int n4x, int n4tot) {
    int i = blockIdx.x * blockDim.x + threadIdx.x;
    if (i >= n4tot) return;
    const bool isw = (i >= n4x);
    const int  j   = isw ? (i - n4x) : i;
    int4 v = isw ? win[j] : xin[j];
#if HAS_TCGEN05
    __nv_bfloat162 p0, p1;
    p0.x = __int2bfloat16_rn(v.x); p0.y = __int2bfloat16_rn(v.y);
    p1.x = __int2bfloat16_rn(v.z); p1.y = __int2bfloat16_rn(v.w);
    uint2 o;
    o.x = *reinterpret_cast<unsigned*>(&p0);
    o.y = *reinterpret_cast<unsigned*>(&p1);
    reinterpret_cast<uint2*>(isw ? wout : xout)[j] = o;
#else
    char4 o;
    o.x = (char)v.x; o.y = (char)v.y; o.z = (char)v.z; o.w = (char)v.w;
    reinterpret_cast<char4*>(isw ? wout : xout)[j] = o;
#endif
}

// ---------------------------------------------------------------------------
// PERSISTENT GEMM, 8-stage SW64 ring + split TMEM-free gates:
// epilogue signals EPIFREE0 after draining cols 0-255 and EPIFREE1 after
// 256-511; the next tile's D0 MMAs start as soon as EPIFREE0 fires, and the
// EPIFREE1 wait is deferred to just before the first D1 MMA — the D1-half
// drain overlaps the next tile's first D0 MMAs.
// ---------------------------------------------------------------------------
__global__ void __launch_bounds__(GTHREADS) __cluster_dims__(CLUSTER, 1, 1)
q8gemm_kernel(
    const __grid_constant__ CUtensorMap tmA,
    const __grid_constant__ CUtensorMap tmB,
    const float* __restrict__ bias,
    const float* __restrict__ xsc,
    const float* __restrict__ wsc,
    float* __restrict__ out,
    int nslots)
{
    extern __shared__ __align__(1024) char smem[];
    const int tid  = threadIdx.x;
    const int wid  = tid >> 5;
    const int lid  = tid & 31;
    const int rank = blockIdx.x & 1;             // cluster rank
    const int slot = blockIdx.x >> 1;            // persistent pair slot

#if HAS_TCGEN05
    const uint32_t sb = smem_u32(smem);

    if (wid == 0) TCGEN05_ALLOC_CG2(sb + SM_TMEMPTR, 512);
    if (tid == 0) {
        #pragma unroll
        for (int s = 0; s < NSTAGE; s++) {
            MBARRIER_INIT(sb + SM_FULL(s), 1);
            MBARRIER_INIT(sb + SM_DONE(s), 1);
            MBARRIER_INIT(sb + SM_PRDY(s), 1);
        }
        MBARRIER_INIT(sb + SM_FINAL, 1);
        MBARRIER_INIT(sb + SM_EPIFREE0, 2);   // one arrive per CTA per tile
        MBARRIER_INIT(sb + SM_EPIFREE1, 2);
    }
    __syncthreads();
    CLUSTER_SYNC();

    uint32_t tbase;
    asm volatile("ld.shared.b32 %0, [%1];" : "=r"(tbase) : "r"(sb + SM_TMEMPTR));

    if (wid == 0) {
        // ================= producer: one continuous TMA stream =================
        if (elect_one_pred()) {
            int g = 0;
            for (int t = slot; t < NT_TOTAL; t += nslots) {
                int m0c, n0; tile_coords(t, rank, m0c, n0);
                for (int ks = 0; ks < NKI; ks++, g++) {
                    const int s = g & (NSTAGE - 1);
                    if (g >= NSTAGE)
                        MBARRIER_WAIT_PARITY(sb + SM_DONE(s), ((g - NSTAGE) >> 3) & 1);
                    MBARRIER_EXPECT_TX(sb + SM_FULL(s), STAGE_BYTES);
                    tma_ld2(sb + SM_A(s),           &tmA, ks * KC, m0c,                   sb + SM_FULL(s));
                    tma_ld2(sb + SM_B(s),           &tmB, ks * KC, n0 + rank * 128,       sb + SM_FULL(s));
                    tma_ld2(sb + SM_B(s) + B_CHUNK, &tmB, ks * KC, n0 + 256 + rank * 128, sb + SM_FULL(s));
                }
            }
        }
    } else if (wid == 1) {
        // ============== control: MMA driver (leader) / forwarder (peer) =========
        if (rank == 0) {
            if (elect_one_pred()) {
                int g = 0, ti = 0;
                for (int t = slot; t < NT_TOTAL; t += nslots, ti++) {
                    if (ti >= 1) {                       // D0 TMEM half free
                        MBARRIER_WAIT_PARITY(sb + SM_EPIFREE0, (ti - 1) & 1);
                        TCGEN05_FENCE_AFTER();
                    }
                    for (int ks = 0; ks < NKI; ks++, g++) {
                        const int s  = g & (NSTAGE - 1);
                        const int ph = (g >> 3) & 1;
                        MBARRIER_WAIT_PARITY(sb + SM_FULL(s), ph);
                        MBARRIER_WAIT_PARITY(sb + SM_PRDY(s), ph);
                        uint64_t ad = make_desc64(sb + SM_A(s));
                        uint64_t b0 = make_desc64(sb + SM_B(s));
                        uint64_t b1 = make_desc64(sb + SM_B(s) + B_CHUNK);
                        const uint32_t e0 = (uint32_t)(ks != 0);
                        // D0 half first
                        mma_bf16_ss_cg2(tbase, ad,     b0,     MMA_IDESC_CG2, e0);
                        mma_bf16_ss_cg2(tbase, ad + 2, b0 + 2, MMA_IDESC_CG2, 1u);
                        // Deferred D1 gate: prev tile's D1 drain overlapped the
                        // D0 MMAs above (fires once per tile, fast path after).
                        if (ks == 0 && ti >= 1) {
                            MBARRIER_WAIT_PARITY(sb + SM_EPIFREE1, (ti - 1) & 1);
                            TCGEN05_FENCE_AFTER();
                        }
                        mma_bf16_ss_cg2(tbase + 256, ad,     b1,     MMA_IDESC_CG2, e0);
                        mma_bf16_ss_cg2(tbase + 256, ad + 2, b1 + 2, MMA_IDESC_CG2, 1u);
                        TCGEN05_COMMIT_MC_CG2(sb + SM_DONE(s), 0x3);
                    }
                    TCGEN05_COMMIT_MC_CG2(sb + SM_FINAL, 0x3);
                }
            }
        } else {
            if (elect_one_pred()) {
                int g = 0;
                for (int t = slot; t < NT_TOTAL; t += nslots)
                    for (int ks = 0; ks < NKI; ks++, g++) {
                        const int s  = g & (NSTAGE - 1);
                        const int ph = (g >> 3) & 1;
                        MBARRIER_WAIT_PARITY(sb + SM_FULL(s), ph);
                        MBARRIER_ARRIVE_CLUSTER(sb + SM_PRDY(s), 0);
                    }
            }
        }
    } else if (wid >= 4) {
        // ======================== epilogue: warps 4-7 ==========================
        float* s_ws = reinterpret_cast<float*>(smem + SM_SCALES);
        float* s_bi = s_ws + TILE_NP;
        const int etid = tid - 128;          // 0..127
        int ti = 0;
        for (int t = slot; t < NT_TOTAL; t += nslots, ti++) {
            int m0c, n0; tile_coords(t, rank, m0c, n0);
            for (int i = etid; i < TILE_NP; i += 128) {
                s_ws[i] = wsc[n0 + i];
                s_bi[i] = bias[n0 + i];
            }
            NAMED_BAR_EPI();
            MBARRIER_WAIT_PARITY(sb + SM_FINAL, ti & 1);
            TCGEN05_FENCE_AFTER();

            const int row = m0c + (wid & 3) * 32 + lid;
            const float xsv = xsc[row];
            float* orow = out + (size_t)row * OUT_F + n0;
            #pragma unroll 1
            for (int half = 0; half < 2; half++) {
                #pragma unroll 1
                for (int cb = half * 8; cb < half * 8 + 8; cb += 2) {  // 2 blocks/wait
                    uint32_t rg[2][32];
                    TCGEN05_LD_32X32B_X32(rg[0], tbase + cb * 32);
                    TCGEN05_LD_32X32B_X32(rg[1], tbase + (cb + 1) * 32);
                    TCGEN05_WAIT_LD();
                    #pragma unroll
                    for (int h = 0; h < 2; h++) {
                        #pragma unroll
                        for (int q = 0; q < 8; q++) {
                            const int c = (cb + h) * 32 + q * 4;
                            float4 v;
                            v.x = fmaf(__uint_as_float(rg[h][q * 4 + 0]), xsv * s_ws[c + 0], s_bi[c + 0]);
                            v.y = fmaf(__uint_as_float(rg[h][q * 4 + 1]), xsv * s_ws[c + 1], s_bi[c + 1]);
                            v.z = fmaf(__uint_as_float(rg[h][q * 4 + 2]), xsv * s_ws[c + 2], s_bi[c + 2]);
                            v.w = fmaf(__uint_as_float(rg[h][q * 4 + 3]), xsv * s_ws[c + 3], s_bi[c + 3]);
                            *reinterpret_cast<float4*>(orow + c) = v;
                        }
                    }
                }
                TCGEN05_FENCE_BEFORE();
                NAMED_BAR_EPI();             // this half fully drained by all warps
                if (wid == 4 && elect_one_pred())
                    MBARRIER_ARRIVE_CLUSTER(half == 0 ? (sb + SM_EPIFREE0)
                                                      : (sb + SM_EPIFREE1), 0);
            }
        }
    }

    __syncthreads();
    if (wid == 0) {
        TCGEN05_RELINQUISH_CG2();
        TCGEN05_DEALLOC_CG2(tbase, 512);
    }
    CLUSTER_SYNC();

#else
    // =================== portable int8 mma.sync fallback ===================
    const int8_t* x8 = reinterpret_cast<const int8_t*>(g_xb);
    const int8_t* w8 = reinterpret_cast<const int8_t*>(g_wb);

    const int AST = 80, BST = 80;
    char* sA = smem;
    char* sB = smem + 128 * AST;
    const uint32_t sAu = smem_u32(sA);
    const uint32_t sBu = smem_u32(sB);
    const int warp_row = (wid & 3) * 32;

    for (int t = slot; t < NT_TOTAL; t += nslots) {
        int m0c, n0; tile_coords(t, rank, m0c, n0);
        for (int nc = 0; nc < 8; nc++) {
            const int nb = n0 + nc * 64;
            int acc[2][8][4];
            #pragma unroll
            for (int a = 0; a < 2; a++)
                #pragma unroll
                for (int b = 0; b < 8; b++)
                    #pragma unroll
                    for (int c = 0; c < 4; c++) acc[a][b][c] = 0;

            for (int kt = 0; kt < 64; kt++) {
                const int k0 = kt * 64;
                __syncthreads();
                if (tid < 128) {
                    const uint4* src = reinterpret_cast<const uint4*>(
                        x8 + (size_t)(m0c + tid) * IN_F + k0);
                    uint4* dst = reinterpret_cast<uint4*>(sA + tid * AST);
                    #pragma unroll
                    for (int j = 0; j < 4; j++) dst[j] = src[j];
                    const int br = tid >> 1, hh = tid & 1;
                    const uint4* src2 = reinterpret_cast<const uint4*>(
                        w8 + (size_t)(nb + br) * IN_F + k0 + hh * 32);
                    uint4* dst2 = reinterpret_cast<uint4*>(sB + br * BST + hh * 32);
                    dst2[0] = src2[0]; dst2[1] = src2[1];
                }
                __syncthreads();

                if (tid < 128) {
                    #pragma unroll
                    for (int s = 0; s < 2; s++) {
                        uint32_t afr[2][4];
                        #pragma unroll
                        for (int mt2 = 0; mt2 < 2; mt2++) {
                            uint32_t addr = sAu +
                                (uint32_t)(warp_row + mt2 * 16 + (lid & 15)) * AST +
                                s * 32 + ((lid >= 16) ? 16 : 0);
                            ldsm_x4(afr[mt2][0], afr[mt2][1], afr[mt2][2], afr[mt2][3], addr);
                        }
                        uint32_t bfr[4][4];
                        #pragma unroll
                        for (int p = 0; p < 4; p++) {
                            uint32_t addr = sBu +
                                (uint32_t)(p * 16 + (lid & 7) + ((lid >= 16) ? 8 : 0)) * BST +
                                s * 32 + ((lid & 8) ? 16 : 0);
                            ldsm_x4(bfr[p][0], bfr[p][1], bfr[p][2], bfr[p][3], addr);
                        }
                        #pragma unroll
                        for (int mt2 = 0; mt2 < 2; mt2++)
                            #pragma unroll
                            for (int nt2 = 0; nt2 < 8; nt2++) {
                                uint32_t bb[2];
                                bb[0] = bfr[nt2 >> 1][(nt2 & 1) ? 2 : 0];
                                bb[1] = bfr[nt2 >> 1][(nt2 & 1) ? 3 : 1];
                                imma16832(acc[mt2][nt2], afr[mt2], bb);
                            }
                    }
                }
            }
            if (tid < 128) {
                #pragma unroll
                for (int mt2 = 0; mt2 < 2; mt2++) {
                    const int r0_ = m0c + warp_row + mt2 * 16 + (lid >> 2);
                    const float xs0 = xsc[r0_], xs1 = xsc[r0_ + 8];
                    #pragma unroll
                    for (int nt2 = 0; nt2 < 8; nt2++) {
                        const int c0 = nb + nt2 * 8 + (lid & 3) * 2;
                        const float w0 = wsc[c0], w1 = wsc[c0 + 1];
                        const float b0 = bias[c0], b1 = bias[c0 + 1];
                        float* o0 = out + (size_t)r0_ * OUT_F + c0;
                        float* o1 = out + (size_t)(r0_ + 8) * OUT_F + c0;
                        o0[0] = fmaf((float)acc[mt2][nt2][0], xs0 * w0, b0);
                        o0[1] = fmaf((float)acc[mt2][nt2][1], xs0 * w1, b1);
                        o1[0] = fmaf((float)acc[mt2][nt2][2], xs1 * w0, b0);
                        o1[1] = fmaf((float)acc[mt2][nt2][3], xs1 * w1, b1);
                    }
                }
            }
        }
    }
#endif
}

// ---------------------------------------------------------------------------
// Host launcher
// ---------------------------------------------------------------------------
typedef CUresult (*tmencode_fn_t)(
    CUtensorMap*, CUtensorMapDataType, cuuint32_t, void*,
    const cuuint64_t*, const cuuint64_t*, const cuuint32_t*, const cuuint32_t*,
    CUtensorMapInterleave, CUtensorMapSwizzle, CUtensorMapL2promotion,
    CUtensorMapFloatOOBfill);

extern "C" void kernel_launch(void* const* d_in, const int* in_sizes, int n_in,
                              void* d_out, int out_size) {
    const int*   x    = (const int*)d_in[0];
    const int*   w    = (const int*)d_in[1];
    const float* bias = (const float*)d_in[2];
    const float* xsc  = (const float*)d_in[3];
    const float* wsc  = (const float*)d_in[4];
    float* out = (float*)d_out;

    void* xb_ptr = nullptr;
    void* wb_ptr = nullptr;
    cudaGetSymbolAddress(&xb_ptr, g_xb);
    cudaGetSymbolAddress(&wb_ptr, g_wb);

    // Fused pre-pass: one launch converts both tensors.
    {
        const int n4x   = TOKENS * IN_F / 4;
        const int n4w   = OUT_F * IN_F / 4;
        const int n4tot = n4x + n4w;
        cvt_fused_kernel<<<(n4tot + 255) / 256, 256>>>(
            (const int4*)x, (const int4*)w, xb_ptr, wb_ptr, n4x, n4tot);
    }

    // TMA descriptors: SW64, 64B inner rows, 128-row boxes (A half / B chunk).
    tmencode_fn_t enc = nullptr;
    {
        void* fn = nullptr;
        cudaDriverEntryPointQueryResult qres;
#if CUDART_VERSION >= 12050
        cudaGetDriverEntryPointByVersion("cuTensorMapEncodeTiled", &fn, 12000,
                                         cudaEnableDefault, &qres);
#else
        cudaGetDriverEntryPoint("cuTensorMapEncodeTiled", &fn,
                                cudaEnableDefault, &qres);
#endif
        enc = (tmencode_fn_t)fn;
    }

    alignas(64) CUtensorMap tmA, tmB;
    if (enc) {
        {
            cuuint64_t dims[2] = {IN_F, TOKENS};
            cuuint64_t strd[1] = {IN_F * 2ull};
            cuuint32_t box[2]  = {KC, 128};             // 32 bf16 = 64B inner
            cuuint32_t es[2]   = {1, 1};
            enc(&tmA, CU_TENSOR_MAP_DATA_TYPE_BFLOAT16, 2, xb_ptr, dims, strd, box, es,
                CU_TENSOR_MAP_INTERLEAVE_NONE, CU_TENSOR_MAP_SWIZZLE_64B,
                CU_TENSOR_MAP_L2_PROMOTION_L2_128B, CU_TENSOR_MAP_FLOAT_OOB_FILL_NONE);
        }
        {
            cuuint64_t dims[2] = {IN_F, OUT_F};
            cuuint64_t strd[1] = {IN_F * 2ull};
            cuuint32_t box[2]  = {KC, 128};
            cuuint32_t es[2]   = {1, 1};
            enc(&tmB, CU_TENSOR_MAP_DATA_TYPE_BFLOAT16, 2, wb_ptr, dims, strd, box, es,
                CU_TENSOR_MAP_INTERLEAVE_NONE, CU_TENSOR_MAP_SWIZZLE_64B,
                CU_TENSOR_MAP_L2_PROMOTION_L2_128B, CU_TENSOR_MAP_FLOAT_OOB_FILL_NONE);
        }
    }

    cudaFuncSetAttribute(q8gemm_kernel,
                         cudaFuncAttributeMaxDynamicSharedMemorySize, SMEM_TOTAL);

    // Persistent grid: exactly one CTA per SM (cluster pairs).
    int sms = 148;
    cudaDeviceGetAttribute(&sms, cudaDevAttrMultiProcessorCount, 0);
    const int nslots = sms / 2;
    const int grid   = nslots * 2;
    q8gemm_kernel<<<grid, GTHREADS, SMEM_TOTAL>>>(tmA, tmB, bias, xsc, wsc, out, nslots);
}

// round 17
// speedup vs baseline: 1.0805x; 1.0013x over previous
#include <cuda_runtime.h>
#include <cuda.h>
#include <cuda_bf16.h>
#include <cstdint>

// ---------------------------------------------------------------------------
// Problem constants
// ---------------------------------------------------------------------------
#define TOKENS 8192
#define IN_F   4096
#define OUT_F  16384

#define TILE_MP 256                  // M per cluster pair (128 per CTA)
#define TILE_NP 512                  // N per cluster pair (2 x N=256 MMAs)
#define GTHREADS 256                 // w0=producer, w1=control, w4-7=epilogue
#define CLUSTER 2
#define NT_TOTAL 1024                // 32 m-pairs x 32 n-tiles

// SW64 atoms: 32 bf16 per stage-row (64B rows)
#define KC     32
#define NKI    (IN_F / KC)           // 128 K-iterations per tile (= 16 blocks of 8)
#define NSTAGE 8

// Per-CTA stage: A 128x64B (8KB) + B 2x128x64B (16KB) = 24KB
#define SM_TMEMPTR 0
#define SM_FULL(s)  (64  + (s) * 8)   // leader: count 2 (tx-arrive + peer arrive)
#define SM_DONE(s)  (192 + (s) * 8)
#define SM_FINAL    448
#define SM_EPIFREE0 456
#define SM_EPIFREE1 464
#define SM_TILES    1024
#define A_BYTES     (128 * KC * 2)            // 8192
#define B_CHUNK     (128 * KC * 2)            // 8192
#define STAGE_BYTES (A_BYTES + 2 * B_CHUNK)   // 24576
#define SM_A(s) (SM_TILES + (s) * STAGE_BYTES)
#define SM_B(s) (SM_A(s) + A_BYTES)
#define SM_SCALES  (SM_TILES + NSTAGE * STAGE_BYTES)     // 197632
#define SMEM_TOTAL (SM_SCALES + 2 * TILE_NP * 4)          // 201728 (1 CTA/SM)

// Arch-specific feature gate: tcgen05 legal only on sm_100a / sm_103a targets.
#if defined(__CUDA_ARCH_FEAT_SM103_ALL) || defined(__CUDA_ARCH_FEAT_SM100_ALL)
#define HAS_TCGEN05 1
#else
#define HAS_TCGEN05 0
#endif

// idesc, kind::f16 cg2: dtype=F32, a=BF16, b=BF16, N=256, M_TOTAL=256.
static constexpr uint32_t MMA_IDESC_CG2 =
    (1u << 4) | (1u << 7) | (1u << 10) | ((256u / 8u) << 17) | ((256u / 16u) << 24);

// Scratch (device-global scratch is the sanctioned no-alloc path).
__device__ __nv_bfloat16 g_xb[(size_t)TOKENS * IN_F];   // 64 MB
__device__ __nv_bfloat16 g_wb[(size_t)OUT_F * IN_F];    // 128 MB

// ---------------------------------------------------------------------------
// Common PTX helpers
// ---------------------------------------------------------------------------
__device__ __forceinline__ uint32_t elect_one_pred() {
    uint32_t pred;
    asm volatile(
        "{\n\t.reg .pred p;\n\telect.sync _|p, 0xFFFFFFFF;\n\t"
        "selp.b32 %0, 1, 0, p;\n\t}" : "=r"(pred));
    return pred;
}

__device__ __forceinline__ uint32_t smem_u32(const void* p) {
    uint32_t a;
    asm("{ .reg .u64 t; cvta.to.shared.u64 t, %1; cvt.u32.u64 %0, t; }"
        : "=r"(a) : "l"(p));
    return a;
}

#define MBARRIER_INIT(addr, cnt) \
    asm volatile("mbarrier.init.shared.b64 [%0], %1;" :: "r"((uint32_t)(addr)), "r"((uint32_t)(cnt)) : "memory")

#define MBARRIER_EXPECT_TX(addr, tx) \
    asm volatile("mbarrier.arrive.expect_tx.shared.b64 _, [%0], %1;" :: "r"((uint32_t)(addr)), "r"((uint32_t)(tx)) : "memory")

// Arrive on the mbarrier at the same SMEM offset in cluster CTA `rank`.
#define MBARRIER_ARRIVE_CLUSTER(local_mbar_addr, target_rank) \
    asm volatile( \
        "{\n\t.reg .b32 remAddr32;\n\t" \
        "mapa.shared::cluster.u32 remAddr32, %0, %1;\n\t" \
        "mbarrier.arrive.shared::cluster.b64 _, [remAddr32];\n\t}" \
        :: "r"((uint32_t)(local_mbar_addr)), "r"((uint32_t)(target_rank)) : "memory")

#define MBARRIER_WAIT_PARITY(mbar_smem_addr, phase_parity) do { \
    uint32_t _mbar = (uint32_t)(mbar_smem_addr); \
    uint32_t _parity = (uint32_t)(phase_parity); \
    uint32_t _done_; \
    asm volatile( \
        "{\n\t.reg .pred p;\n\t" \
        "mbarrier.try_wait.parity.acquire.cta.shared::cta.b64 p, [%1], %2;\n\t" \
        "selp.b32 %0, 1, 0, p;\n\t}" \
        : "=r"(_done_) : "r"(_mbar), "r"(_parity) : "memory"); \
    if (!_done_) { \
        asm volatile( \
            "{\n\t.reg .pred P1;\n\t" \
            "WAIT_LOOP_%=:\n\t" \
            "mbarrier.try_wait.parity.acquire.cta.shared::cta.b64 P1, [%0], %1, 0x989680;\n\t" \
            "@P1 bra.uni WAIT_DONE_%=;\n\t" \
            "bra.uni WAIT_LOOP_%=;\n\t" \
            "WAIT_DONE_%=:\n\t}" \
            :: "r"(_mbar), "r"(_parity) : "memory"); \
    } \
} while (0)

#define CLUSTER_SYNC() do { \
    asm volatile("barrier.cluster.arrive.aligned;" ::: "memory"); \
    asm volatile("barrier.cluster.wait.aligned;"   ::: "memory"); \
} while (0)

#define NAMED_BAR_EPI() asm volatile("bar.sync 1, 128;" ::: "memory")

// ---------------------------------------------------------------------------
// tcgen05 cg2 macros
// ---------------------------------------------------------------------------
#define TCGEN05_ALLOC_CG2(smem_result_addr, nCols) \
    asm volatile("tcgen05.alloc.cta_group::2.sync.aligned.shared::cta.b32 [%0], %1;" \
        :: "r"((uint32_t)(smem_result_addr)), "r"((uint32_t)(nCols)) : "memory")

#define TCGEN05_DEALLOC_CG2(tmem_addr, nCols) \
    asm volatile("tcgen05.dealloc.cta_group::2.sync.aligned.b32 %0, %1;" \
        :: "r"(tmem_addr), "r"((uint32_t)(nCols)))

#define TCGEN05_RELINQUISH_CG2() \
    asm volatile("tcgen05.relinquish_alloc_permit.cta_group::2.sync.aligned;")

#define TCGEN05_COMMIT_MC_CG2(mbar_smem_addr, mask) \
    asm volatile("tcgen05.commit.cta_group::2.mbarrier::arrive::one.shared::cluster.multicast::cluster.b64 [%0], %1;" \
        :: "r"((uint32_t)(mbar_smem_addr)), "h"((uint16_t)(mask)) : "memory")

#define TCGEN05_WAIT_LD() \
    asm volatile("tcgen05.wait::ld.sync.aligned;" ::: "memory")

#define TCGEN05_FENCE_BEFORE() \
    asm volatile("tcgen05.fence::before_thread_sync;" ::: "memory")

#define TCGEN05_FENCE_AFTER() \
    asm volatile("tcgen05.fence::after_thread_sync;" ::: "memory")

#define TCGEN05_LD_32X32B_X32(r, tmem_addr) \
    asm volatile( \
        "tcgen05.ld.sync.aligned.32x32b.x32.b32 " \
        "{%0, %1, %2, %3, %4, %5, %6, %7, " \
        " %8, %9, %10, %11, %12, %13, %14, %15, " \
        " %16, %17, %18, %19, %20, %21, %22, %23, " \
        " %24, %25, %26, %27, %28, %29, %30, %31}, [%32];" \
        : "=r"((r)[0]),  "=r"((r)[1]),  "=r"((r)[2]),  "=r"((r)[3]), \
          "=r"((r)[4]),  "=r"((r)[5]),  "=r"((r)[6]),  "=r"((r)[7]), \
          "=r"((r)[8]),  "=r"((r)[9]),  "=r"((r)[10]), "=r"((r)[11]), \
          "=r"((r)[12]), "=r"((r)[13]), "=r"((r)[14]), "=r"((r)[15]), \
          "=r"((r)[16]), "=r"((r)[17]), "=r"((r)[18]), "=r"((r)[19]), \
          "=r"((r)[20]), "=r"((r)[21]), "=r"((r)[22]), "=r"((r)[23]), \
          "=r"((r)[24]), "=r"((r)[25]), "=r"((r)[26]), "=r"((r)[27]), \
          "=r"((r)[28]), "=r"((r)[29]), "=r"((r)[30]), "=r"((r)[31]) \
        : "r"(tmem_addr))

// SW64 K-major descriptor: layout=4, version=1, SBO=32 (512B atom), LBO=1.
static constexpr unsigned long long SMEM_DESC_BASE_SW64 =
    (4ull << 61) | (1ull << 46) | (32ull << 32) | (1ull << 16);

__device__ __forceinline__ uint64_t make_desc64(uint32_t smem_addr) {
    return SMEM_DESC_BASE_SW64 | ((uint64_t)(smem_addr >> 4) & 0x3FFFull);
}

// Band-local tile mapping (8-n-tile bands keep a 32MB B band L2-resident).
__device__ __forceinline__ void tile_coords(int t, int rank, int& m0c, int& n0) {
    const int band = t >> 8;           // 256 tiles per band
    const int r    = t & 255;
    const int mtp  = r >> 3;
    const int nt   = (band << 3) + (r & 7);
    m0c = mtp * TILE_MP + rank * 128;
    n0  = nt * TILE_NP;
}

#if HAS_TCGEN05
// cg2 bf16 SS MMA (8 zero regs for disable-output-lane).
__device__ __forceinline__ void mma_bf16_ss_cg2(uint32_t d_tmem, uint64_t a_desc,
                                                uint64_t b_desc, uint32_t idesc,
                                                uint32_t enable_d) {
    asm volatile(
        "{\n\t.reg .pred p;\n\t"
        "setp.ne.u32 p, %5, 0;\n\t"
        "tcgen05.mma.cta_group::2.kind::f16 [%0], %1, %2, %3, "
        "{%4, %4, %4, %4, %4, %4, %4, %4}, p;\n\t}"
        :: "r"(d_tmem), "l"(a_desc), "l"(b_desc), "r"(idesc), "r"(0u), "r"(enable_d)
        : "memory");
}

__device__ __forceinline__ void tma_ld2(uint32_t smem_addr, const CUtensorMap* tmap,
                                        int cx, int cy, uint32_t mbar) {
    asm volatile(
        "cp.async.bulk.tensor.2d.shared::cta.global.tile.mbarrier::complete_tx::bytes "
        "[%0], [%1, {%2, %3}], [%4];"
        :: "r"(smem_addr), "l"(tmap), "r"(cx), "r"(cy), "r"(mbar) : "memory");
}
#endif

// ---------------------------------------------------------------------------
// Fallback helpers: ldmatrix + int8 mma.sync (family-portable)
// ---------------------------------------------------------------------------
__device__ __forceinline__ void ldsm_x4(uint32_t& r0, uint32_t& r1,
                                        uint32_t& r2, uint32_t& r3, uint32_t addr) {
    asm volatile("ldmatrix.sync.aligned.m8n8.x4.shared.b16 {%0,%1,%2,%3}, [%4];"
                 : "=r"(r0), "=r"(r1), "=r"(r2), "=r"(r3) : "r"(addr));
}

__device__ __forceinline__ void imma16832(int* c, const uint32_t* a, const uint32_t* b) {
    asm volatile(
        "mma.sync.aligned.m16n8k32.row.col.s32.s8.s8.s32 "
        "{%0,%1,%2,%3}, {%4,%5,%6,%7}, {%8,%9}, {%0,%1,%2,%3};"
        : "+r"(c[0]), "+r"(c[1]), "+r"(c[2]), "+r"(c[3])
        : "r"(a[0]), "r"(a[1]), "r"(a[2]), "r"(a[3]), "r"(b[0]), "r"(b[1]));
}

// ---------------------------------------------------------------------------
// FUSED pre-pass: one launch converts BOTH tensors (x then w).
// ---------------------------------------------------------------------------
__global__ void cvt_fused_kernel(const int4* __restrict__ xin, const int4* __restrict__ win,
                                 void* __restrict__ xout, void* __restrict__ wout,
                                 int n4x, int n4tot) {
    int i = blockIdx.x * blockDim.x + threadIdx.x;
    if (i >= n4tot) return;
    const bool isw = (i >= n4x);
    const int  j   = isw ? (i - n4x) : i;
    int4 v = isw ? win[j] : xin[j];
#if HAS_TCGEN05
    __nv_bfloat162 p0, p1;
    p0.x = __int2bfloat16_rn(v.x); p0.y = __int2bfloat16_rn(v.y);
    p1.x = __int2bfloat16_rn(v.z); p1.y = __int2bfloat16_rn(v.w);
    uint2 o;
    o.x = *reinterpret_cast<unsigned*>(&p0);
    o.y = *reinterpret_cast<unsigned*>(&p1);
    reinterpret_cast<uint2*>(isw ? wout : xout)[j] = o;
#else
    char4 o;
    o.x = (char)v.x; o.y = (char)v.y; o.z = (char)v.z; o.w = (char)v.w;
    reinterpret_cast<char4*>(isw ? wout : xout)[j] = o;
#endif
}

// ---------------------------------------------------------------------------
// PERSISTENT GEMM. Driver critical path minimized (R16 profile: tensor idle
// from driver overrun): leader FULL barriers carry BOTH producer expect_tx
// and peer readiness (count 2) -> ONE wait per iteration; all 24 stage
// descriptors precomputed in registers; K-loop unrolled in aligned 8-stage
// blocks (phase = blk&1, compile-time shaped).
// ---------------------------------------------------------------------------
__global__ void __launch_bounds__(GTHREADS) __cluster_dims__(CLUSTER, 1, 1)
q8gemm_kernel(
    const __grid_constant__ CUtensorMap tmA,
    const __grid_constant__ CUtensorMap tmB,
    const float* __restrict__ bias,
    const float* __restrict__ xsc,
    const float* __restrict__ wsc,
    float* __restrict__ out,
    int nslots)
{
    extern __shared__ __align__(1024) char smem[];
    const int tid  = threadIdx.x;
    const int wid  = tid >> 5;
    const int lid  = tid & 31;
    const int rank = blockIdx.x & 1;             // cluster rank
    const int slot = blockIdx.x >> 1;            // persistent pair slot

#if HAS_TCGEN05
    const uint32_t sb = smem_u32(smem);

    if (wid == 0) TCGEN05_ALLOC_CG2(sb + SM_TMEMPTR, 512);
    if (tid == 0) {
        #pragma unroll
        for (int s = 0; s < NSTAGE; s++) {
            // Leader FULL completes on (producer expect_tx arrive + peer arrive
            // + tx bytes); peer FULL is local-only (producer arrive + tx).
            MBARRIER_INIT(sb + SM_FULL(s), (rank == 0) ? 2 : 1);
            MBARRIER_INIT(sb + SM_DONE(s), 1);
        }
        MBARRIER_INIT(sb + SM_FINAL, 1);
        MBARRIER_INIT(sb + SM_EPIFREE0, 2);   // one arrive per CTA per tile
        MBARRIER_INIT(sb + SM_EPIFREE1, 2);
    }
    __syncthreads();
    CLUSTER_SYNC();

    uint32_t tbase;
    asm volatile("ld.shared.b32 %0, [%1];" : "=r"(tbase) : "r"(sb + SM_TMEMPTR));

    if (wid == 0) {
        // ================= producer: one continuous TMA stream =================
        if (elect_one_pred()) {
            int g = 0;
            for (int t = slot; t < NT_TOTAL; t += nslots) {
                int m0c, n0; tile_coords(t, rank, m0c, n0);
                for (int ks = 0; ks < NKI; ks++, g++) {
                    const int s = g & (NSTAGE - 1);
                    if (g >= NSTAGE)
                        MBARRIER_WAIT_PARITY(sb + SM_DONE(s), ((g - NSTAGE) >> 3) & 1);
                    MBARRIER_EXPECT_TX(sb + SM_FULL(s), STAGE_BYTES);
                    tma_ld2(sb + SM_A(s),           &tmA, ks * KC, m0c,                   sb + SM_FULL(s));
                    tma_ld2(sb + SM_B(s),           &tmB, ks * KC, n0 + rank * 128,       sb + SM_FULL(s));
                    tma_ld2(sb + SM_B(s) + B_CHUNK, &tmB, ks * KC, n0 + 256 + rank * 128, sb + SM_FULL(s));
                }
            }
        }
    } else if (wid == 1) {
        // ============== control: MMA driver (leader) / forwarder (peer) =========
        if (rank == 0) {
            if (elect_one_pred()) {
                // Precompute all stage descriptors once (registers, const-indexed).
                uint64_t adv[NSTAGE], b0v[NSTAGE], b1v[NSTAGE];
                #pragma unroll
                for (int s = 0; s < NSTAGE; s++) {
                    adv[s] = make_desc64(sb + SM_A(s));
                    b0v[s] = make_desc64(sb + SM_B(s));
                    b1v[s] = make_desc64(sb + SM_B(s) + B_CHUNK);
                }
                int ti = 0;
                for (int t = slot; t < NT_TOTAL; t += nslots, ti++) {
                    if (ti >= 1) {                       // D0 TMEM half free
                        MBARRIER_WAIT_PARITY(sb + SM_EPIFREE0, (ti - 1) & 1);
                        TCGEN05_FENCE_AFTER();
                    }
                    // Block 0 (phase 0): handles enable_d=0 + deferred D1 gate.
                    #pragma unroll
                    for (int s = 0; s < NSTAGE; s++) {
                        MBARRIER_WAIT_PARITY(sb + SM_FULL(s), 0);
                        const uint32_t e0 = (uint32_t)(s != 0);
                        mma_bf16_ss_cg2(tbase, adv[s],     b0v[s],     MMA_IDESC_CG2, e0);
                        mma_bf16_ss_cg2(tbase, adv[s] + 2, b0v[s] + 2, MMA_IDESC_CG2, 1u);
                        if (s == 0 && ti >= 1) {         // D1 half free (overlapped)
                            MBARRIER_WAIT_PARITY(sb + SM_EPIFREE1, (ti - 1) & 1);
                            TCGEN05_FENCE_AFTER();
                        }
                        mma_bf16_ss_cg2(tbase + 256, adv[s],     b1v[s],     MMA_IDESC_CG2, e0);
                        mma_bf16_ss_cg2(tbase + 256, adv[s] + 2, b1v[s] + 2, MMA_IDESC_CG2, 1u);
                        TCGEN05_COMMIT_MC_CG2(sb + SM_DONE(s), 0x3);
                    }
                    // Blocks 1..15: steady state, phase = blk&1.
                    #pragma unroll 1
                    for (int blk = 1; blk < NKI / NSTAGE; blk++) {
                        const int ph = blk & 1;
                        #pragma unroll
                        for (int s = 0; s < NSTAGE; s++) {
                            MBARRIER_WAIT_PARITY(sb + SM_FULL(s), ph);
                            mma_bf16_ss_cg2(tbase,       adv[s],     b0v[s],     MMA_IDESC_CG2, 1u);
                            mma_bf16_ss_cg2(tbase,       adv[s] + 2, b0v[s] + 2, MMA_IDESC_CG2, 1u);
                            mma_bf16_ss_cg2(tbase + 256, adv[s],     b1v[s],     MMA_IDESC_CG2, 1u);
                            mma_bf16_ss_cg2(tbase + 256, adv[s] + 2, b1v[s] + 2, MMA_IDESC_CG2, 1u);
                            TCGEN05_COMMIT_MC_CG2(sb + SM_DONE(s), 0x3);
                        }
                    }
                    TCGEN05_COMMIT_MC_CG2(sb + SM_FINAL, 0x3);
                }
            }
        } else {
            // Peer: forward each stage's readiness straight onto the LEADER's
            // FULL barrier (its second arrive).
            if (elect_one_pred()) {
                int g = 0;
                for (int t = slot; t < NT_TOTAL; t += nslots)
                    for (int ks = 0; ks < NKI; ks++, g++) {
                        const int s  = g & (NSTAGE - 1);
                        const int ph = (g >> 3) & 1;
                        MBARRIER_WAIT_PARITY(sb + SM_FULL(s), ph);
                        MBARRIER_ARRIVE_CLUSTER(sb + SM_FULL(s), 0);
                    }
            }
        }
    } else if (wid >= 4) {
        // ======================== epilogue: warps 4-7 ==========================
        float* s_ws = reinterpret_cast<float*>(smem + SM_SCALES);
        float* s_bi = s_ws + TILE_NP;
        const int etid = tid - 128;          // 0..127
        int ti = 0;
        for (int t = slot; t < NT_TOTAL; t += nslots, ti++) {
            int m0c, n0; tile_coords(t, rank, m0c, n0);
            for (int i = etid; i < TILE_NP; i += 128) {
                s_ws[i] = wsc[n0 + i];
                s_bi[i] = bias[n0 + i];
            }
            NAMED_BAR_EPI();
            MBARRIER_WAIT_PARITY(sb + SM_FINAL, ti & 1);
            TCGEN05_FENCE_AFTER();

            const int row = m0c + (wid & 3) * 32 + lid;
            const float xsv = xsc[row];
            float* orow = out + (size_t)row * OUT_F + n0;
            #pragma unroll 1
            for (int half = 0; half < 2; half++) {
                #pragma unroll 1
                for (int cb = half * 8; cb < half * 8 + 8; cb += 2) {  // 2 blocks/wait
                    uint32_t rg[2][32];
                    TCGEN05_LD_32X32B_X32(rg[0], tbase + cb * 32);
                    TCGEN05_LD_32X32B_X32(rg[1], tbase + (cb + 1) * 32);
                    TCGEN05_WAIT_LD();
                    #pragma unroll
                    for (int h = 0; h < 2; h++) {
                        #pragma unroll
                        for (int q = 0; q < 8; q++) {
                            const int c = (cb + h) * 32 + q * 4;
                            float4 v;
                            v.x = fmaf(__uint_as_float(rg[h][q * 4 + 0]), xsv * s_ws[c + 0], s_bi[c + 0]);
                            v.y = fmaf(__uint_as_float(rg[h][q * 4 + 1]), xsv * s_ws[c + 1], s_bi[c + 1]);
                            v.z = fmaf(__uint_as_float(rg[h][q * 4 + 2]), xsv * s_ws[c + 2], s_bi[c + 2]);
                            v.w = fmaf(__uint_as_float(rg[h][q * 4 + 3]), xsv * s_ws[c + 3], s_bi[c + 3]);
                            *reinterpret_cast<float4*>(orow + c) = v;
                        }
                    }
                }
                TCGEN05_FENCE_BEFORE();
                NAMED_BAR_EPI();             // this half fully drained by all warps
                if (wid == 4 && elect_one_pred())
                    MBARRIER_ARRIVE_CLUSTER(half == 0 ? (sb + SM_EPIFREE0)
                                                      : (sb + SM_EPIFREE1), 0);
            }
        }
    }

    __syncthreads();
    if (wid == 0) {
        TCGEN05_RELINQUISH_CG2();
        TCGEN05_DEALLOC_CG2(tbase, 512);
    }
    CLUSTER_SYNC();

#else
    // =================== portable int8 mma.sync fallback ===================
    const int8_t* x8 = reinterpret_cast<const int8_t*>(g_xb);
    const int8_t* w8 = reinterpret_cast<const int8_t*>(g_wb);

    const int AST = 80, BST = 80;
    char* sA = smem;
    char* sB = smem + 128 * AST;
    const uint32_t sAu = smem_u32(sA);
    const uint32_t sBu = smem_u32(sB);
    const int warp_row = (wid & 3) * 32;

    for (int t = slot; t < NT_TOTAL; t += nslots) {
        int m0c, n0; tile_coords(t, rank, m0c, n0);
        for (int nc = 0; nc < 8; nc++) {
            const int nb = n0 + nc * 64;
            int acc[2][8][4];
            #pragma unroll
            for (int a = 0; a < 2; a++)
                #pragma unroll
                for (int b = 0; b < 8; b++)
                    #pragma unroll
                    for (int c = 0; c < 4; c++) acc[a][b][c] = 0;

            for (int kt = 0; kt < 64; kt++) {
                const int k0 = kt * 64;
                __syncthreads();
                if (tid < 128) {
                    const uint4* src = reinterpret_cast<const uint4*>(
                        x8 + (size_t)(m0c + tid) * IN_F + k0);
                    uint4* dst = reinterpret_cast<uint4*>(sA + tid * AST);
                    #pragma unroll
                    for (int j = 0; j < 4; j++) dst[j] = src[j];
                    const int br = tid >> 1, hh = tid & 1;
                    const uint4* src2 = reinterpret_cast<const uint4*>(
                        w8 + (size_t)(nb + br) * IN_F + k0 + hh * 32);
                    uint4* dst2 = reinterpret_cast<uint4*>(sB + br * BST + hh * 32);
                    dst2[0] = src2[0]; dst2[1] = src2[1];
                }
                __syncthreads();

                if (tid < 128) {
                    #pragma unroll
                    for (int s = 0; s < 2; s++) {
                        uint32_t afr[2][4];
                        #pragma unroll
                        for (int mt2 = 0; mt2 < 2; mt2++) {
                            uint32_t addr = sAu +
                                (uint32_t)(warp_row + mt2 * 16 + (lid & 15)) * AST +
                                s * 32 + ((lid >= 16) ? 16 : 0);
                            ldsm_x4(afr[mt2][0], afr[mt2][1], afr[mt2][2], afr[mt2][3], addr);
                        }
                        uint32_t bfr[4][4];
                        #pragma unroll
                        for (int p = 0; p < 4; p++) {
                            uint32_t addr = sBu +
                                (uint32_t)(p * 16 + (lid & 7) + ((lid >= 16) ? 8 : 0)) * BST +
                                s * 32 + ((lid & 8) ? 16 : 0);
                            ldsm_x4(bfr[p][0], bfr[p][1], bfr[p][2], bfr[p][3], addr);
                        }
                        #pragma unroll
                        for (int mt2 = 0; mt2 < 2; mt2++)
                            #pragma unroll
                            for (int nt2 = 0; nt2 < 8; nt2++) {
                                uint32_t bb[2];
                                bb[0] = bfr[nt2 >> 1][(nt2 & 1) ? 2 : 0];
                                bb[1] = bfr[nt2 >> 1][(nt2 & 1) ? 3 : 1];
                                imma16832(acc[mt2][nt2], afr[mt2], bb);
                            }
                    }
                }
            }
            if (tid < 128) {
                #pragma unroll
                for (int mt2 = 0; mt2 < 2; mt2++) {
                    const int r0_ = m0c + warp_row + mt2 * 16 + (lid >> 2);
                    const float xs0 = xsc[r0_], xs1 = xsc[r0_ + 8];
                    #pragma unroll
                    for (int nt2 = 0; nt2 < 8; nt2++) {
                        const int c0 = nb + nt2 * 8 + (lid & 3) * 2;
                        const float w0 = wsc[c0], w1 = wsc[c0 + 1];
                        const float b0 = bias[c0], b1 = bias[c0 + 1];
                        float* o0 = out + (size_t)r0_ * OUT_F + c0;
                        float* o1 = out + (size_t)(r0_ + 8) * OUT_F + c0;
                        o0[0] = fmaf((float)acc[mt2][nt2][0], xs0 * w0, b0);
                        o0[1] = fmaf((float)acc[mt2][nt2][1], xs0 * w1, b1);
                        o1[0] = fmaf((float)acc[mt2][nt2][2], xs1 * w0, b0);
                        o1[1] = fmaf((float)acc[mt2][nt2][3], xs1 * w1, b1);
                    }
                }
            }
        }
    }
#endif
}

// ---------------------------------------------------------------------------
// Host launcher
// ---------------------------------------------------------------------------
typedef CUresult (*tmencode_fn_t)(
    CUtensorMap*, CUtensorMapDataType, cuuint32_t, void*,
    const cuuint64_t*, const cuuint64_t*, const cuuint32_t*, const cuuint32_t*,
    CUtensorMapInterleave, CUtensorMapSwizzle, CUtensorMapL2promotion,
    CUtensorMapFloatOOBfill);

extern "C" void kernel_launch(void* const* d_in, const int* in_sizes, int n_in,
                              void* d_out, int out_size) {
    const int*   x    = (const int*)d_in[0];
    const int*   w    = (const int*)d_in[1];
    const float* bias = (const float*)d_in[2];
    const float* xsc  = (const float*)d_in[3];
    const float* wsc  = (const float*)d_in[4];
    float* out = (float*)d_out;

    void* xb_ptr = nullptr;
    void* wb_ptr = nullptr;
    cudaGetSymbolAddress(&xb_ptr, g_xb);
    cudaGetSymbolAddress(&wb_ptr, g_wb);

    // Fused pre-pass: one launch converts both tensors.
    {
        const int n4x   = TOKENS * IN_F / 4;
        const int n4w   = OUT_F * IN_F / 4;
        const int n4tot = n4x + n4w;
        cvt_fused_kernel<<<(n4tot + 255) / 256, 256>>>(
            (const int4*)x, (const int4*)w, xb_ptr, wb_ptr, n4x, n4tot);
    }

    // TMA descriptors: SW64, 64B inner rows, 128-row boxes (A half / B chunk).
    tmencode_fn_t enc = nullptr;
    {
        void* fn = nullptr;
        cudaDriverEntryPointQueryResult qres;
#if CUDART_VERSION >= 12050
        cudaGetDriverEntryPointByVersion("cuTensorMapEncodeTiled", &fn, 12000,
                                         cudaEnableDefault, &qres);
#else
        cudaGetDriverEntryPoint("cuTensorMapEncodeTiled", &fn,
                                cudaEnableDefault, &qres);
#endif
        enc = (tmencode_fn_t)fn;
    }

    alignas(64) CUtensorMap tmA, tmB;
    if (enc) {
        {
            cuuint64_t dims[2] = {IN_F, TOKENS};
            cuuint64_t strd[1] = {IN_F * 2ull};
            cuuint32_t box[2]  = {KC, 128};             // 32 bf16 = 64B inner
            cuuint32_t es[2]   = {1, 1};
            enc(&tmA, CU_TENSOR_MAP_DATA_TYPE_BFLOAT16, 2, xb_ptr, dims, strd, box, es,
                CU_TENSOR_MAP_INTERLEAVE_NONE, CU_TENSOR_MAP_SWIZZLE_64B,
                CU_TENSOR_MAP_L2_PROMOTION_L2_128B, CU_TENSOR_MAP_FLOAT_OOB_FILL_NONE);
        }
        {
            cuuint64_t dims[2] = {IN_F, OUT_F};
            cuuint64_t strd[1] = {IN_F * 2ull};
            cuuint32_t box[2]  = {KC, 128};
            cuuint32_t es[2]   = {1, 1};
            enc(&tmB, CU_TENSOR_MAP_DATA_TYPE_BFLOAT16, 2, wb_ptr, dims, strd, box, es,
                CU_TENSOR_MAP_INTERLEAVE_NONE, CU_TENSOR_MAP_SWIZZLE_64B,
                CU_TENSOR_MAP_L2_PROMOTION_L2_128B, CU_TENSOR_MAP_FLOAT_OOB_FILL_NONE);
        }
    }

    cudaFuncSetAttribute(q8gemm_kernel,
                         cudaFuncAttributeMaxDynamicSharedMemorySize, SMEM_TOTAL);

    // Persistent grid: exactly one CTA per SM (cluster pairs).
    int sms = 148;
    cudaDeviceGetAttribute(&sms, cudaDevAttrMultiProcessorCount, 0);
    const int nslots = sms / 2;
    const int grid   = nslots * 2;
    q8gemm_kernel<<<grid, GTHREADS, SMEM_TOTAL>>>(tmA, tmB, bias, xsc, wsc, out, nslots);
}